// round 9
// baseline (speedup 1.0000x reference)
#include <cuda_runtime.h>
#include <cstdint>
#include <math.h>

// ---------------- problem constants ----------------
namespace {
constexpr int Bb    = 8;
constexpr int Ss    = 1024;
constexpr int FIN   = 256;
constexpr int Ee    = 512;
constexpr int INNER = 1024;
constexpr int NHh   = 4;
constexpr int DHd   = 256;
constexpr int KSk   = 4;
constexpr int ROWS  = Bb * Ss;      // 8192
constexpr int BNH   = Bb * NHh;     // 32

// smem tile geometry (256 threads, 8 warps: 2x4 grid, 64x32 per warp)
constexpr int KT      = 32;
constexpr int ROWSTR  = 36;
constexpr int TILE_F  = 128 * ROWSTR;        // 4608
constexpr int STAGE_F = 2 * TILE_F;          // 9216
constexpr int GSMEM   = 2 * STAGE_F * 4;               // 73728 (2-stage)
constexpr int QKSMEM  = GSMEM + 3 * 128 * 4;           // +cf/rf/rfl
}

// ---------------- scratch ----------------
__device__ float g_xp[(size_t)ROWS * Ee];
__device__ float g_h [(size_t)ROWS * Ee];
__device__ float g_up[(size_t)ROWS * 2 * INNER];
__device__ float g_xc[(size_t)ROWS * INNER];
__device__ float g_q [(size_t)ROWS * INNER];
__device__ float g_k [(size_t)ROWS * INNER];
__device__ float g_v [(size_t)ROWS * INNER];
__device__ float g_vT[(size_t)BNH * DHd * Ss];
__device__ float g_ig[BNH * Ss];
__device__ float g_fg[BNH * Ss];
__device__ float g_e [BNH * Ss];
__device__ float g_pm[BNH * Ss];
__device__ float g_md[BNH * Ss];
__device__ float g_n [BNH * Ss];
__device__ float g_C [(size_t)BNH * Ss * Ss];
__device__ float g_hh[(size_t)BNH * Ss * DHd];
__device__ float g_hs[(size_t)ROWS * INNER];
__device__ float g_y [(size_t)ROWS * Ee];
__device__ float g_xr[(size_t)ROWS * FIN];
__device__ float g_Wi[(size_t)Ee * FIN];
__device__ float g_Wu[(size_t)2 * INNER * Ee];
__device__ float g_Wd[(size_t)Ee * INNER];

// ---------------- helpers ----------------
__device__ __forceinline__ float tf32r(float x) {
    uint32_t u;
    asm("cvt.rna.tf32.f32 %0, %1;" : "=r"(u) : "f"(x));
    return __uint_as_float(u);
}
__device__ __forceinline__ void mma_tf32(float* c, const uint32_t* a, const uint32_t* b) {
    asm volatile(
        "mma.sync.aligned.m16n8k8.row.col.f32.tf32.tf32.f32 "
        "{%0,%1,%2,%3}, {%4,%5,%6,%7}, {%8,%9}, {%0,%1,%2,%3};"
        : "+f"(c[0]), "+f"(c[1]), "+f"(c[2]), "+f"(c[3])
        : "r"(a[0]), "r"(a[1]), "r"(a[2]), "r"(a[3]), "r"(b[0]), "r"(b[1]));
}
__device__ __forceinline__ uint32_t smem_u32(const void* p) {
    uint32_t a;
    asm("{ .reg .u64 t; cvta.to.shared.u64 t, %1; cvt.u32.u64 %0, t; }" : "=r"(a) : "l"(p));
    return a;
}
#define CP16(dst, src) \
    asm volatile("cp.async.cg.shared.global [%0], [%1], 16;" :: "r"(dst), "l"(src) : "memory")
#define CP_COMMIT() asm volatile("cp.async.commit_group;" ::: "memory")
#define CP_WAIT(n)  asm volatile("cp.async.wait_group %0;" :: "n"(n) : "memory")

__device__ __forceinline__ float blockReduceSum(float v) {
    __shared__ float sh[33];
    int lane = threadIdx.x & 31, wid = threadIdx.x >> 5;
    #pragma unroll
    for (int o = 16; o; o >>= 1) v += __shfl_down_sync(0xffffffffu, v, o);
    if (lane == 0) sh[wid] = v;
    __syncthreads();
    int nw = blockDim.x >> 5;
    float t = (threadIdx.x < nw) ? sh[threadIdx.x] : 0.f;
    if (wid == 0) {
        #pragma unroll
        for (int o = 16; o; o >>= 1) t += __shfl_down_sync(0xffffffffu, t, o);
        if (lane == 0) sh[32] = t;
    }
    __syncthreads();
    float r = sh[32];
    __syncthreads();
    return r;
}

// ---------------- GEMM machinery (256 threads, 2x4 warps, 64x32/warp) -------
__device__ __forceinline__ void g_load_tile(uint32_t sb, int stage,
                                            const float* A, const float* B,
                                            int kt, int lda, int ldb) {
    int lrow = threadIdx.x >> 1;
    int lch  = (threadIdx.x & 1) * 4;
    uint32_t abase = sb + (uint32_t)(stage * STAGE_F) * 4 + lrow * (ROWSTR * 4);
    uint32_t bbase = abase + TILE_F * 4;
    const float* ap = A + (long)lrow * lda + kt * KT + lch * 4;
    const float* bp = B + (long)lrow * ldb + kt * KT + lch * 4;
    #pragma unroll
    for (int i = 0; i < 4; ++i) {
        CP16(abase + (lch + i) * 16, ap + i * 4);
        CP16(bbase + (lch + i) * 16, bp + i * 4);
    }
}

__device__ __forceinline__ void g_compute_tile(const float* As, const float* Bs,
                                               int wm, int wn, int gid, int tig,
                                               float acc[4][4][4]) {
    #pragma unroll
    for (int ks = 0; ks < 4; ++ks) {
        int kc = ks * 8;
        uint32_t a[4][4], b[4][2];
        #pragma unroll
        for (int mi = 0; mi < 4; ++mi) {
            int r = wm * 64 + mi * 16 + gid;
            a[mi][0] = __float_as_uint(As[r * ROWSTR + kc + tig]);
            a[mi][1] = __float_as_uint(As[(r + 8) * ROWSTR + kc + tig]);
            a[mi][2] = __float_as_uint(As[r * ROWSTR + kc + tig + 4]);
            a[mi][3] = __float_as_uint(As[(r + 8) * ROWSTR + kc + tig + 4]);
        }
        #pragma unroll
        for (int ni = 0; ni < 4; ++ni) {
            int n = wn * 32 + ni * 8 + gid;
            b[ni][0] = __float_as_uint(Bs[n * ROWSTR + kc + tig]);
            b[ni][1] = __float_as_uint(Bs[n * ROWSTR + kc + tig + 4]);
        }
        #pragma unroll
        for (int mi = 0; mi < 4; ++mi)
            #pragma unroll
            for (int ni = 0; ni < 4; ++ni)
                mma_tf32(acc[mi][ni], a[mi], b[ni]);
    }
}

// 2-stage mainloop, ONE __syncthreads per K-tile.
// load(kt+1) (issued after the sync) writes stage (kt+1)&1, which was last
// read by compute(kt-1) -- ordered by this same sync. Race-free.
#define GEMM_MAINLOOP(Aptr, Bptr, LDA, LDB)                                  \
    g_load_tile(sb, 0, Aptr, Bptr, 0, LDA, LDB);                             \
    CP_COMMIT();                                                             \
    for (int kt = 0; kt < nT; ++kt) {                                        \
        CP_WAIT(0);                                                          \
        __syncthreads();                                                     \
        if (kt + 1 < nT) {                                                   \
            g_load_tile(sb, (kt + 1) & 1, Aptr, Bptr, kt + 1, LDA, LDB);     \
            CP_COMMIT();                                                     \
        }                                                                    \
        g_compute_tile(sm + (kt & 1) * STAGE_F,                              \
                       sm + (kt & 1) * STAGE_F + TILE_F,                     \
                       wm, wn, gid, tig, acc);                               \
    }

// ---------------- general GEMM: C = A(M,K) * B(N,K)^T [+bias] --------------
template<int TRI>   // TRI=0 full, TRI=2 K limited to (by+1)*128
__global__ void __launch_bounds__(256, 3)
mma_gemm(const float* __restrict__ Ag, const float* __restrict__ Bg,
         float* __restrict__ Cg, const float* __restrict__ bias,
         int K, int lda, int ldb, int ldc,
         long aOffB, long aOffN, long bOffB, long bOffN, long cOffB, long cOffN) {
    int bx = blockIdx.x, by = blockIdx.y, z = blockIdx.z;
    extern __shared__ float sm[];
    uint32_t sb = smem_u32(sm);
    const float* A = Ag + (long)(z >> 2) * aOffB + (long)(z & 3) * aOffN + (long)by * 128 * lda;
    const float* B = Bg + (long)(z >> 2) * bOffB + (long)(z & 3) * bOffN + (long)bx * 128 * ldb;
    float*       Cp = Cg + (long)(z >> 2) * cOffB + (long)(z & 3) * cOffN;

    int Keff = (TRI == 2) ? min(K, (by + 1) * 128) : K;
    int nT = Keff / KT;

    int tid = threadIdx.x, wid = tid >> 5, lane = tid & 31;
    int wm = wid >> 2, wn = wid & 3;
    int gid = lane >> 2, tig = lane & 3;

    float acc[4][4][4] = {};
    GEMM_MAINLOOP(A, B, lda, ldb)

    long m0 = (long)by * 128 + wm * 64;
    long n0 = (long)bx * 128 + wn * 32;
    #pragma unroll
    for (int mi = 0; mi < 4; ++mi) {
        #pragma unroll
        for (int ni = 0; ni < 4; ++ni) {
            long r = m0 + mi * 16 + gid;
            long c = n0 + ni * 8 + tig * 2;
            float b0 = bias ? bias[c] : 0.f, b1 = bias ? bias[c + 1] : 0.f;
            float2 v0 = {acc[mi][ni][0] + b0, acc[mi][ni][1] + b1};
            float2 v1 = {acc[mi][ni][2] + b0, acc[mi][ni][3] + b1};
            *(float2*)(Cp + r * ldc + c) = v0;
            *(float2*)(Cp + (r + 8) * ldc + c) = v1;
        }
    }
}

// ---------------- fused QK^T + decay + mask + rowsum ------------------------
__global__ void __launch_bounds__(256, 3)
qk_fused(const float* __restrict__ qg, const float* __restrict__ kg,
         float* __restrict__ Cg, const float* __restrict__ eg,
         const float* __restrict__ pmg, float* __restrict__ nsum) {
    int bx = blockIdx.x, by = blockIdx.y, z = blockIdx.z;
    if (bx > by) return;
    extern __shared__ float sm[];
    uint32_t sb = smem_u32(sm);
    int tid = threadIdx.x, wid = tid >> 5, lane = tid & 31;
    int wm = wid >> 2, wn = wid & 3;
    int gid = lane >> 2, tig = lane & 3;

    const float* A = qg + (long)(z >> 2) * Ss * INNER + (long)(z & 3) * DHd + (long)by * 128 * INNER;
    const float* B = kg + (long)(z >> 2) * Ss * INNER + (long)(z & 3) * DHd + (long)bx * 128 * INNER;
    float* Cp = Cg + (long)z * Ss * Ss;
    const float* e_r  = eg  + (long)z * Ss;
    const float* pm_r = pmg + (long)z * Ss;
    int s0 = by * 128, t0 = bx * 128;
    float P = pm_r[s0 + 127];

    float* cf  = sm + 2 * STAGE_F;
    float* rf  = cf + 128;
    float* rfl = rf + 128;
    if (tid < 128) {
        int j = tid;
        cf[j] = expf(e_r[t0 + j] - P) * 0.0625f;
        float rl = P - pm_r[s0 + j];
        rfl[j] = rl;
        rf[j] = expf(fminf(rl, 60.f));
    }

    float acc[4][4][4] = {};
    const int nT = DHd / KT;   // 8
    GEMM_MAINLOOP(A, B, INNER, INNER)

    bool diag = (bx == by);
    #pragma unroll
    for (int mi = 0; mi < 4; ++mi) {
        int r0 = wm * 64 + mi * 16 + gid;
        float rl0 = rfl[r0], rl1 = rfl[r0 + 8];
        bool  sl0 = rl0 > 60.f, sl1 = rl1 > 60.f;
        float rv0 = rf[r0], rv1 = rf[r0 + 8];
        float pm0 = P - rl0, pm1 = P - rl1;
        float sum0 = 0.f, sum1 = 0.f;
        #pragma unroll
        for (int ni = 0; ni < 4; ++ni) {
            int cidx = wn * 32 + ni * 8 + tig * 2;
            float c0 = cf[cidx], c1 = cf[cidx + 1];
            float v00, v01, v10, v11;
            if (!sl0) { v00 = acc[mi][ni][0] * c0 * rv0; v01 = acc[mi][ni][1] * c1 * rv0; }
            else {
                v00 = acc[mi][ni][0] * 0.0625f * expf(e_r[t0 + cidx]     - pm0);
                v01 = acc[mi][ni][1] * 0.0625f * expf(e_r[t0 + cidx + 1] - pm0);
            }
            if (!sl1) { v10 = acc[mi][ni][2] * c0 * rv1; v11 = acc[mi][ni][3] * c1 * rv1; }
            else {
                v10 = acc[mi][ni][2] * 0.0625f * expf(e_r[t0 + cidx]     - pm1);
                v11 = acc[mi][ni][3] * 0.0625f * expf(e_r[t0 + cidx + 1] - pm1);
            }
            if (diag) {
                if (cidx     > r0)     v00 = 0.f;
                if (cidx + 1 > r0)     v01 = 0.f;
                if (cidx     > r0 + 8) v10 = 0.f;
                if (cidx + 1 > r0 + 8) v11 = 0.f;
            }
            sum0 += v00 + v01;
            sum1 += v10 + v11;
            float2 w0 = {tf32r(v00), tf32r(v01)};
            float2 w1 = {tf32r(v10), tf32r(v11)};
            *(float2*)(Cp + (long)(s0 + r0)     * Ss + t0 + cidx) = w0;
            *(float2*)(Cp + (long)(s0 + r0 + 8) * Ss + t0 + cidx) = w1;
        }
        sum0 += __shfl_xor_sync(0xffffffffu, sum0, 1);
        sum0 += __shfl_xor_sync(0xffffffffu, sum0, 2);
        sum1 += __shfl_xor_sync(0xffffffffu, sum1, 1);
        sum1 += __shfl_xor_sync(0xffffffffu, sum1, 2);
        if (tig == 0) {
            atomicAdd(&nsum[(long)z * Ss + s0 + r0], sum0);
            atomicAdd(&nsum[(long)z * Ss + s0 + r0 + 8], sum1);
        }
    }
}

// ---------------- prep: tf32-round all operands + zero g_n ------------------
__global__ void prep_all(const float* __restrict__ x, const float* __restrict__ Wi,
                         const float* __restrict__ Wu, const float* __restrict__ Wd) {
    const int n1 = ROWS * FIN / 4, n2 = Ee * FIN / 4,
              n3 = 2 * INNER * Ee / 4, n4 = Ee * INNER / 4, n5 = BNH * Ss / 4;
    int i = blockIdx.x * 256 + threadIdx.x;
    const float4* src; float4* dst; int j = i;
    if (j < n1)            { src = (const float4*)x;  dst = (float4*)g_xr; }
    else if ((j -= n1) < n2) { src = (const float4*)Wi; dst = (float4*)g_Wi; }
    else if ((j -= n2) < n3) { src = (const float4*)Wu; dst = (float4*)g_Wu; }
    else if ((j -= n3) < n4) { src = (const float4*)Wd; dst = (float4*)g_Wd; }
    else if ((j -= n4) < n5) { ((float4*)g_n)[j] = make_float4(0, 0, 0, 0); return; }
    else return;
    float4 v = src[j];
    v.x = tf32r(v.x); v.y = tf32r(v.y); v.z = tf32r(v.z); v.w = tf32r(v.w);
    dst[j] = v;
}

// ---------------- row LayerNorm; RND=1 rounds output to tf32 ---------------
template<int RND>
__global__ void ln_rows(const float* __restrict__ in, const float* __restrict__ w,
                        float* __restrict__ out, int W) {
    long row = blockIdx.x;
    const float* p = in + row * (long)W;
    float s = 0.f, s2 = 0.f;
    for (int j = threadIdx.x; j < W; j += blockDim.x) { float v = p[j]; s += v; s2 += v * v; }
    s  = blockReduceSum(s);
    s2 = blockReduceSum(s2);
    float mu  = s / W;
    float var = s2 / W - mu * mu;
    float r = rsqrtf(var + 1e-5f);
    for (int j = threadIdx.x; j < W; j += blockDim.x) {
        float o = (p[j] - mu) * r * w[j];
        out[row * (long)W + j] = RND ? tf32r(o) : o;
    }
}

// ---------------- fused conv+SiLU+headwise (row-local) ----------------------
__global__ void __launch_bounds__(256)
conv_head(const float* __restrict__ cw, const float* __restrict__ cb,
          const float* __restrict__ Wq, const float* __restrict__ Wk,
          const float* __restrict__ Wv) {
    __shared__ float xc_s[INNER];
    long row = blockIdx.x;
    int  t   = (int)(row & (Ss - 1));
    int tid = threadIdx.x;
    #pragma unroll
    for (int l = 0; l < 4; ++l) {
        int c = tid + l * 256;
        float acc = cb[c];
        #pragma unroll
        for (int j = 0; j < KSk; ++j) {
            int dt = j - (KSk - 1);
            if (t + dt >= 0)
                acc += g_up[(row + dt) * (2 * INNER) + c] * cw[c * KSk + j];
        }
        float s = acc / (1.f + expf(-acc));
        xc_s[c] = s;
        g_xc[row * INNER + c] = s;
    }
    __syncthreads();
    int nb = tid;
    long base = row * INNER + nb * 4;
    float4 xm = *(const float4*)&g_up[row * (2 * INNER) + nb * 4];
    float xc4[4] = {xc_s[nb * 4], xc_s[nb * 4 + 1], xc_s[nb * 4 + 2], xc_s[nb * 4 + 3]};
    float xm4[4] = {xm.x, xm.y, xm.z, xm.w};
    float qo[4], ko[4], vo[4];
    #pragma unroll
    for (int o = 0; o < 4; ++o) {
        float q = 0.f, k = 0.f, v = 0.f;
        #pragma unroll
        for (int i = 0; i < 4; ++i) {
            q += xc4[i] * Wq[nb * 16 + o * 4 + i];
            k += xc4[i] * Wk[nb * 16 + o * 4 + i];
            v += xm4[i] * Wv[nb * 16 + o * 4 + i];
        }
        qo[o] = tf32r(q); ko[o] = tf32r(k); vo[o] = tf32r(v);
    }
    *(float4*)&g_q[base] = *(float4*)qo;
    *(float4*)&g_k[base] = *(float4*)ko;
    *(float4*)&g_v[base] = *(float4*)vo;
}

// ---------------- per-head v transpose --------------------------------------
__global__ void transpose_v() {
    __shared__ float t[32][33];
    int bn = blockIdx.z;
    int s0 = blockIdx.x * 32, d0 = blockIdx.y * 32;
    int tx = threadIdx.x, ty = threadIdx.y;
    t[ty][tx] = g_v[((long)(bn >> 2) * Ss + s0 + ty) * INNER + (bn & 3) * DHd + d0 + tx];
    __syncthreads();
    g_vT[((long)bn * DHd + d0 + ty) * Ss + s0 + tx] = t[tx][ty];
}

// ---------------- gate projections ------------------------------------------
__global__ void gates(const float* __restrict__ Wig, const float* __restrict__ big,
                      const float* __restrict__ Wfg, const float* __restrict__ bfg) {
    long row = blockIdx.x;
    float aI[4] = {0, 0, 0, 0}, aF[4] = {0, 0, 0, 0};
    for (int c = threadIdx.x; c < INNER; c += blockDim.x) {
        float qv = g_q[row * INNER + c];
        float kv = g_k[row * INNER + c];
        float vv = g_v[row * INNER + c];
        #pragma unroll
        for (int n = 0; n < 4; ++n) {
            const float* wi = Wig + (long)n * 3 * INNER;
            const float* wf = Wfg + (long)n * 3 * INNER;
            aI[n] += qv * wi[c] + kv * wi[INNER + c] + vv * wi[2 * INNER + c];
            aF[n] += qv * wf[c] + kv * wf[INNER + c] + vv * wf[2 * INNER + c];
        }
    }
    int b = (int)(row >> 10), s = (int)(row & 1023);
    #pragma unroll
    for (int n = 0; n < 4; ++n) {
        float si = blockReduceSum(aI[n]);
        float sf = blockReduceSum(aF[n]);
        if (threadIdx.x == 0) {
            g_ig[(b * NHh + n) * Ss + s] = si + big[n];
            g_fg[(b * NHh + n) * Ss + s] = sf + bfg[n];
        }
    }
}

// ---------------- parallel gate scan (one block per bn, 1024 threads) -------
__global__ void __launch_bounds__(1024)
gate_scan_par() {
    __shared__ float wsum[32];
    int bn = blockIdx.x;
    int t = threadIdx.x, lane = t & 31, wid = t >> 5;
    float f  = g_fg[bn * Ss + t];
    float lf = fminf(f, 0.f) - log1pf(expf(-fabsf(f)));   // log_sigmoid

    float v = lf;
    #pragma unroll
    for (int o = 1; o < 32; o <<= 1) {
        float nv = __shfl_up_sync(0xffffffffu, v, o);
        if (lane >= o) v += nv;
    }
    if (lane == 31) wsum[wid] = v;
    __syncthreads();
    if (wid == 0) {
        float w = wsum[lane];
        #pragma unroll
        for (int o = 1; o < 32; o <<= 1) {
            float nv = __shfl_up_sync(0xffffffffu, w, o);
            if (lane >= o) w += nv;
        }
        wsum[lane] = w;
    }
    __syncthreads();
    float a = v + (wid > 0 ? wsum[wid - 1] : 0.f);

    float e = g_ig[bn * Ss + t] - a;
    __syncthreads();

    float m = e;
    #pragma unroll
    for (int o = 1; o < 32; o <<= 1) {
        float nv = __shfl_up_sync(0xffffffffu, m, o);
        if (lane >= o) m = fmaxf(m, nv);
    }
    if (lane == 31) wsum[wid] = m;
    __syncthreads();
    if (wid == 0) {
        float w = wsum[lane];
        #pragma unroll
        for (int o = 1; o < 32; o <<= 1) {
            float nv = __shfl_up_sync(0xffffffffu, w, o);
            if (lane >= o) w = fmaxf(w, nv);
        }
        wsum[lane] = w;
    }
    __syncthreads();
    float pm = (wid > 0) ? fmaxf(m, wsum[wid - 1]) : m;

    g_e [bn * Ss + t] = e;
    g_pm[bn * Ss + t] = pm;
    g_md[bn * Ss + t] = a + pm;
}

// ---------------- per-head LN + 1/n + skip + SiLU(z) gate -------------------
__global__ void mhln_combine(const float* __restrict__ mw, const float* __restrict__ skip) {
    int s  = blockIdx.x;
    int bn = blockIdx.y;
    int b = bn >> 2, n = bn & 3;
    int d = threadIdx.x;
    float rs = g_n[bn * Ss + s];
    float nn = fmaxf(fabsf(rs), expf(-g_md[bn * Ss + s]));
    float inv = 1.f / (nn + 1e-6f);
    size_t hrow = ((size_t)bn * Ss + s) * DHd;
    float x  = g_hh[hrow + d] * inv;
    float su = blockReduceSum(x);
    float s2 = blockReduceSum(x * x);
    float mu  = su / DHd;
    float var = s2 / DHd - mu * mu;
    float hn = (x - mu) * rsqrtf(var + 1e-5f) * mw[n * DHd + d];
    int c = n * DHd + d;
    size_t row = (size_t)(b * Ss + s);
    float xc = g_xc[row * INNER + c];
    float z  = g_up[row * (2 * INNER) + INNER + c];
    float sz = z / (1.f + expf(-z));
    g_hs[row * INNER + c] = tf32r((hn + skip[c] * xc) * sz);
}

// ---------------- out = LN(res + y) -> d_out --------------------------------
__global__ void add_ln_out(const float* __restrict__ w, float* __restrict__ out) {
    long row = blockIdx.x;
    float vals[2];
    float s = 0.f, s2 = 0.f;
    #pragma unroll
    for (int l = 0; l < 2; ++l) {
        int j = threadIdx.x + l * 256;
        float v = g_xp[row * Ee + j] + g_y[row * Ee + j];
        vals[l] = v; s += v; s2 += v * v;
    }
    s  = blockReduceSum(s);
    s2 = blockReduceSum(s2);
    float mu  = s / Ee;
    float var = s2 / Ee - mu * mu;
    float r = rsqrtf(var + 1e-5f);
    #pragma unroll
    for (int l = 0; l < 2; ++l) {
        int j = threadIdx.x + l * 256;
        out[row * Ee + j] = (vals[l] - mu) * r * w[j];
    }
}

// ---------------- launch ----------------------------------------------------
extern "C" void kernel_launch(void* const* d_in, const int* /*in_sizes*/, int /*n_in*/,
                              void* d_out, int /*out_size*/) {
    const float* x         = (const float*)d_in[0];
    const float* W_in      = (const float*)d_in[1];
    const float* b_in      = (const float*)d_in[2];
    const float* ln1_w     = (const float*)d_in[3];
    const float* W_up      = (const float*)d_in[4];
    const float* conv_w    = (const float*)d_in[5];
    const float* conv_b    = (const float*)d_in[6];
    const float* Wq        = (const float*)d_in[7];
    const float* Wk        = (const float*)d_in[8];
    const float* Wv        = (const float*)d_in[9];
    const float* W_ig      = (const float*)d_in[10];
    const float* b_ig      = (const float*)d_in[11];
    const float* W_fg      = (const float*)d_in[12];
    const float* b_fg      = (const float*)d_in[13];
    const float* mhln_w    = (const float*)d_in[14];
    const float* skip      = (const float*)d_in[15];
    const float* W_down    = (const float*)d_in[16];
    const float* ln_post_w = (const float*)d_in[17];
    float* out = (float*)d_out;

    void *pxp, *ph, *pup, *pq, *pk, *pvT, *pC, *phh, *phs, *py;
    void *pxr, *pWi, *pWu, *pWd, *pe, *ppm, *pn;
    cudaGetSymbolAddress(&pxp, g_xp);
    cudaGetSymbolAddress(&ph,  g_h);
    cudaGetSymbolAddress(&pup, g_up);
    cudaGetSymbolAddress(&pq,  g_q);
    cudaGetSymbolAddress(&pk,  g_k);
    cudaGetSymbolAddress(&pvT, g_vT);
    cudaGetSymbolAddress(&pC,  g_C);
    cudaGetSymbolAddress(&phh, g_hh);
    cudaGetSymbolAddress(&phs, g_hs);
    cudaGetSymbolAddress(&py,  g_y);
    cudaGetSymbolAddress(&pxr, g_xr);
    cudaGetSymbolAddress(&pWi, g_Wi);
    cudaGetSymbolAddress(&pWu, g_Wu);
    cudaGetSymbolAddress(&pWd, g_Wd);
    cudaGetSymbolAddress(&pe,  g_e);
    cudaGetSymbolAddress(&ppm, g_pm);
    cudaGetSymbolAddress(&pn,  g_n);

    cudaFuncSetAttribute(mma_gemm<0>, cudaFuncAttributeMaxDynamicSharedMemorySize, GSMEM);
    cudaFuncSetAttribute(mma_gemm<2>, cudaFuncAttributeMaxDynamicSharedMemorySize, GSMEM);
    cudaFuncSetAttribute(qk_fused,    cudaFuncAttributeMaxDynamicSharedMemorySize, QKSMEM);

    // 0. prep: tf32-round operands, zero g_n
    {
        int total = ROWS * FIN / 4 + Ee * FIN / 4 + 2 * INNER * Ee / 4
                  + Ee * INNER / 4 + BNH * Ss / 4;
        prep_all<<<(total + 255) / 256, 256>>>(x, W_in, W_up, W_down);
    }

    // 1. xp = x @ W_in^T + b_in
    mma_gemm<0><<<dim3(Ee / 128, ROWS / 128, 1), 256, GSMEM>>>(
        (const float*)pxr, (const float*)pWi, (float*)pxp, b_in,
        FIN, FIN, FIN, Ee, 0, 0, 0, 0, 0, 0);

    // 2. h = LN(xp), tf32
    ln_rows<1><<<ROWS, 256>>>((const float*)pxp, ln1_w, (float*)ph, Ee);

    // 3. up = h @ W_up^T
    mma_gemm<0><<<dim3(2 * INNER / 128, ROWS / 128, 1), 256, GSMEM>>>(
        (const float*)ph, (const float*)pWu, (float*)pup, nullptr,
        Ee, Ee, Ee, 2 * INNER, 0, 0, 0, 0, 0, 0);

    // 4. fused conv+SiLU+headwise
    conv_head<<<ROWS, 256>>>(conv_w, conv_b, Wq, Wk, Wv);

    // 5. gates
    gates<<<ROWS, 256>>>(W_ig, b_ig, W_fg, b_fg);

    // 6. parallel gate scan
    gate_scan_par<<<BNH, 1024>>>();

    // 6b. v transpose
    transpose_v<<<dim3(Ss / 32, DHd / 32, BNH), dim3(32, 32)>>>();

    // 7. fused QK^T * decay + rowsum
    qk_fused<<<dim3(Ss / 128, Ss / 128, BNH), 256, QKSMEM>>>(
        (const float*)pq, (const float*)pk, (float*)pC,
        (const float*)pe, (const float*)ppm, (float*)pn);

    // 8. hh = C @ vT^T per head (K limited to causal extent)
    mma_gemm<2><<<dim3(DHd / 128, Ss / 128, BNH), 256, GSMEM>>>(
        (const float*)pC, (const float*)pvT, (float*)phh, nullptr,
        Ss, Ss, Ss, DHd,
        4L * Ss * Ss, (long)Ss * Ss,
        4L * DHd * Ss, (long)DHd * Ss,
        4L * Ss * DHd, (long)Ss * DHd);

    // 9. per-head LN + 1/n + combine
    mhln_combine<<<dim3(Ss, BNH), 256>>>(mhln_w, skip);

    // 10. y = h_state @ W_down^T
    mma_gemm<0><<<dim3(Ee / 128, ROWS / 128, 1), 256, GSMEM>>>(
        (const float*)phs, (const float*)pWd, (float*)py, nullptr,
        INNER, INNER, INNER, Ee, 0, 0, 0, 0, 0, 0);

    // 11. out = LN(res + y)
    add_ln_out<<<ROWS, 256>>>(ln_post_w, out);
}

// round 10
// speedup vs baseline: 1.3236x; 1.3236x over previous
#include <cuda_runtime.h>
#include <cstdint>
#include <math.h>

// ---------------- problem constants ----------------
namespace {
constexpr int Bb    = 8;
constexpr int Ss    = 1024;
constexpr int FIN   = 256;
constexpr int Ee    = 512;
constexpr int INNER = 1024;
constexpr int NHh   = 4;
constexpr int DHd   = 256;
constexpr int KSk   = 4;
constexpr int ROWS  = Bb * Ss;      // 8192
constexpr int BNH   = Bb * NHh;     // 32

// smem tile geometry (256 threads, 8 warps: 2x4 grid, 64x32 per warp)
constexpr int KT      = 32;
constexpr int ROWSTR  = 36;
constexpr int TILE_F  = 128 * ROWSTR;        // 4608
constexpr int STAGE_F = 2 * TILE_F;          // 9216
constexpr int NSTAGE  = 3;
constexpr int GSMEM   = NSTAGE * STAGE_F * 4;          // 110592
constexpr int QKSMEM  = GSMEM + 3 * 128 * 4;           // +cf/rf/rfl
}

// ---------------- scratch ----------------
__device__ float g_xp[(size_t)ROWS * Ee];
__device__ float g_h [(size_t)ROWS * Ee];
__device__ float g_up[(size_t)ROWS * 2 * INNER];
__device__ float g_xc[(size_t)ROWS * INNER];
__device__ float g_q [(size_t)ROWS * INNER];
__device__ float g_k [(size_t)ROWS * INNER];
__device__ float g_v [(size_t)ROWS * INNER];
__device__ float g_vT[(size_t)BNH * DHd * Ss];
__device__ float g_ig[BNH * Ss];
__device__ float g_fg[BNH * Ss];
__device__ float g_e [BNH * Ss];
__device__ float g_pm[BNH * Ss];
__device__ float g_md[BNH * Ss];
__device__ float g_n [BNH * Ss];
__device__ float g_C [(size_t)BNH * Ss * Ss];
__device__ float g_hh[(size_t)BNH * Ss * DHd];
__device__ float g_hs[(size_t)ROWS * INNER];
__device__ float g_y [(size_t)ROWS * Ee];
__device__ float g_xr[(size_t)ROWS * FIN];
__device__ float g_Wi[(size_t)Ee * FIN];
__device__ float g_Wu[(size_t)2 * INNER * Ee];
__device__ float g_Wd[(size_t)Ee * INNER];

// ---------------- helpers ----------------
__device__ __forceinline__ float tf32r(float x) {
    uint32_t u;
    asm("cvt.rna.tf32.f32 %0, %1;" : "=r"(u) : "f"(x));
    return __uint_as_float(u);
}
__device__ __forceinline__ void mma_tf32(float* c, const uint32_t* a, const uint32_t* b) {
    asm volatile(
        "mma.sync.aligned.m16n8k8.row.col.f32.tf32.tf32.f32 "
        "{%0,%1,%2,%3}, {%4,%5,%6,%7}, {%8,%9}, {%0,%1,%2,%3};"
        : "+f"(c[0]), "+f"(c[1]), "+f"(c[2]), "+f"(c[3])
        : "r"(a[0]), "r"(a[1]), "r"(a[2]), "r"(a[3]), "r"(b[0]), "r"(b[1]));
}
__device__ __forceinline__ uint32_t smem_u32(const void* p) {
    uint32_t a;
    asm("{ .reg .u64 t; cvta.to.shared.u64 t, %1; cvt.u32.u64 %0, t; }" : "=r"(a) : "l"(p));
    return a;
}
#define CP16(dst, src) \
    asm volatile("cp.async.cg.shared.global [%0], [%1], 16;" :: "r"(dst), "l"(src) : "memory")
#define CP_COMMIT() asm volatile("cp.async.commit_group;" ::: "memory")
#define CP_WAIT(n)  asm volatile("cp.async.wait_group %0;" :: "n"(n) : "memory")

__device__ __forceinline__ float blockReduceSum(float v) {
    __shared__ float sh[33];
    int lane = threadIdx.x & 31, wid = threadIdx.x >> 5;
    #pragma unroll
    for (int o = 16; o; o >>= 1) v += __shfl_down_sync(0xffffffffu, v, o);
    if (lane == 0) sh[wid] = v;
    __syncthreads();
    int nw = blockDim.x >> 5;
    float t = (threadIdx.x < nw) ? sh[threadIdx.x] : 0.f;
    if (wid == 0) {
        #pragma unroll
        for (int o = 16; o; o >>= 1) t += __shfl_down_sync(0xffffffffu, t, o);
        if (lane == 0) sh[32] = t;
    }
    __syncthreads();
    float r = sh[32];
    __syncthreads();
    return r;
}

// ---------------- GEMM machinery (256 threads, 2x4 warps, 64x32/warp) -------
__device__ __forceinline__ void g_load_tile(uint32_t sb, int stage,
                                            const float* A, const float* B,
                                            int kt, int lda, int ldb) {
    int lrow = threadIdx.x >> 1;
    int lch  = (threadIdx.x & 1) * 4;
    uint32_t abase = sb + (uint32_t)(stage * STAGE_F) * 4 + lrow * (ROWSTR * 4);
    uint32_t bbase = abase + TILE_F * 4;
    const float* ap = A + (long)lrow * lda + kt * KT + lch * 4;
    const float* bp = B + (long)lrow * ldb + kt * KT + lch * 4;
    #pragma unroll
    for (int i = 0; i < 4; ++i) {
        CP16(abase + (lch + i) * 16, ap + i * 4);
        CP16(bbase + (lch + i) * 16, bp + i * 4);
    }
}

__device__ __forceinline__ void g_compute_tile(const float* As, const float* Bs,
                                               int wm, int wn, int gid, int tig,
                                               float acc[4][4][4]) {
    #pragma unroll
    for (int ks = 0; ks < 4; ++ks) {
        int kc = ks * 8;
        uint32_t a[4][4], b[4][2];
        #pragma unroll
        for (int mi = 0; mi < 4; ++mi) {
            int r = wm * 64 + mi * 16 + gid;
            a[mi][0] = __float_as_uint(As[r * ROWSTR + kc + tig]);
            a[mi][1] = __float_as_uint(As[(r + 8) * ROWSTR + kc + tig]);
            a[mi][2] = __float_as_uint(As[r * ROWSTR + kc + tig + 4]);
            a[mi][3] = __float_as_uint(As[(r + 8) * ROWSTR + kc + tig + 4]);
        }
        #pragma unroll
        for (int ni = 0; ni < 4; ++ni) {
            int n = wn * 32 + ni * 8 + gid;
            b[ni][0] = __float_as_uint(Bs[n * ROWSTR + kc + tig]);
            b[ni][1] = __float_as_uint(Bs[n * ROWSTR + kc + tig + 4]);
        }
        #pragma unroll
        for (int mi = 0; mi < 4; ++mi)
            #pragma unroll
            for (int ni = 0; ni < 4; ++ni)
                mma_tf32(acc[mi][ni], a[mi], b[ni]);
    }
}

// 3-stage mainloop (R7-proven): one __syncthreads per K-tile; CP_WAIT(1)
// keeps one group in flight; load(kt+2) overlaps compute(kt).
#define GEMM_MAINLOOP(Aptr, Bptr, LDA, LDB)                                  \
    g_load_tile(sb, 0, Aptr, Bptr, 0, LDA, LDB);                             \
    CP_COMMIT();                                                             \
    if (nT > 1) { g_load_tile(sb, 1, Aptr, Bptr, 1, LDA, LDB); CP_COMMIT(); }\
    for (int kt = 0; kt < nT; ++kt) {                                        \
        if (kt + 1 < nT) { CP_WAIT(1); } else { CP_WAIT(0); }                \
        __syncthreads();                                                     \
        int nx = kt + 2;                                                     \
        if (nx < nT) { g_load_tile(sb, nx % 3, Aptr, Bptr, nx, LDA, LDB);    \
                       CP_COMMIT(); }                                        \
        g_compute_tile(sm + (kt % 3) * STAGE_F,                              \
                       sm + (kt % 3) * STAGE_F + TILE_F,                     \
                       wm, wn, gid, tig, acc);                               \
    }

// ---------------- general GEMM: C = A(M,K) * B(N,K)^T [+bias] --------------
template<int TRI>   // TRI=0 full, TRI=2 K limited to (by+1)*128
__global__ void __launch_bounds__(256)
mma_gemm(const float* __restrict__ Ag, const float* __restrict__ Bg,
         float* __restrict__ Cg, const float* __restrict__ bias,
         int K, int lda, int ldb, int ldc,
         long aOffB, long aOffN, long bOffB, long bOffN, long cOffB, long cOffN) {
    int bx = blockIdx.x, by = blockIdx.y, z = blockIdx.z;
    extern __shared__ float sm[];
    uint32_t sb = smem_u32(sm);
    const float* A = Ag + (long)(z >> 2) * aOffB + (long)(z & 3) * aOffN + (long)by * 128 * lda;
    const float* B = Bg + (long)(z >> 2) * bOffB + (long)(z & 3) * bOffN + (long)bx * 128 * ldb;
    float*       Cp = Cg + (long)(z >> 2) * cOffB + (long)(z & 3) * cOffN;

    int Keff = (TRI == 2) ? min(K, (by + 1) * 128) : K;
    int nT = Keff / KT;

    int tid = threadIdx.x, wid = tid >> 5, lane = tid & 31;
    int wm = wid >> 2, wn = wid & 3;
    int gid = lane >> 2, tig = lane & 3;

    float acc[4][4][4] = {};
    GEMM_MAINLOOP(A, B, lda, ldb)

    long m0 = (long)by * 128 + wm * 64;
    long n0 = (long)bx * 128 + wn * 32;
    #pragma unroll
    for (int mi = 0; mi < 4; ++mi) {
        #pragma unroll
        for (int ni = 0; ni < 4; ++ni) {
            long r = m0 + mi * 16 + gid;
            long c = n0 + ni * 8 + tig * 2;
            float b0 = bias ? bias[c] : 0.f, b1 = bias ? bias[c + 1] : 0.f;
            float2 v0 = {acc[mi][ni][0] + b0, acc[mi][ni][1] + b1};
            float2 v1 = {acc[mi][ni][2] + b0, acc[mi][ni][3] + b1};
            *(float2*)(Cp + r * ldc + c) = v0;
            *(float2*)(Cp + (r + 8) * ldc + c) = v1;
        }
    }
}

// ---------------- fused QK^T + decay + mask + rowsum ------------------------
__global__ void __launch_bounds__(256)
qk_fused(const float* __restrict__ qg, const float* __restrict__ kg,
         float* __restrict__ Cg, const float* __restrict__ eg,
         const float* __restrict__ pmg, float* __restrict__ nsum) {
    int bx = blockIdx.x, by = blockIdx.y, z = blockIdx.z;
    if (bx > by) return;
    extern __shared__ float sm[];
    uint32_t sb = smem_u32(sm);
    int tid = threadIdx.x, wid = tid >> 5, lane = tid & 31;
    int wm = wid >> 2, wn = wid & 3;
    int gid = lane >> 2, tig = lane & 3;

    const float* A = qg + (long)(z >> 2) * Ss * INNER + (long)(z & 3) * DHd + (long)by * 128 * INNER;
    const float* B = kg + (long)(z >> 2) * Ss * INNER + (long)(z & 3) * DHd + (long)bx * 128 * INNER;
    float* Cp = Cg + (long)z * Ss * Ss;
    const float* e_r  = eg  + (long)z * Ss;
    const float* pm_r = pmg + (long)z * Ss;
    int s0 = by * 128, t0 = bx * 128;
    float P = pm_r[s0 + 127];

    float* cf  = sm + NSTAGE * STAGE_F;
    float* rf  = cf + 128;
    float* rfl = rf + 128;
    if (tid < 128) {
        int j = tid;
        cf[j] = expf(e_r[t0 + j] - P) * 0.0625f;
        float rl = P - pm_r[s0 + j];
        rfl[j] = rl;
        rf[j] = expf(fminf(rl, 60.f));
    }

    float acc[4][4][4] = {};
    const int nT = DHd / KT;   // 8
    GEMM_MAINLOOP(A, B, INNER, INNER)

    bool diag = (bx == by);
    #pragma unroll
    for (int mi = 0; mi < 4; ++mi) {
        int r0 = wm * 64 + mi * 16 + gid;
        float rl0 = rfl[r0], rl1 = rfl[r0 + 8];
        bool  sl0 = rl0 > 60.f, sl1 = rl1 > 60.f;
        float rv0 = rf[r0], rv1 = rf[r0 + 8];
        float pm0 = P - rl0, pm1 = P - rl1;
        float sum0 = 0.f, sum1 = 0.f;
        #pragma unroll
        for (int ni = 0; ni < 4; ++ni) {
            int cidx = wn * 32 + ni * 8 + tig * 2;
            float c0 = cf[cidx], c1 = cf[cidx + 1];
            float v00, v01, v10, v11;
            if (!sl0) { v00 = acc[mi][ni][0] * c0 * rv0; v01 = acc[mi][ni][1] * c1 * rv0; }
            else {
                v00 = acc[mi][ni][0] * 0.0625f * expf(e_r[t0 + cidx]     - pm0);
                v01 = acc[mi][ni][1] * 0.0625f * expf(e_r[t0 + cidx + 1] - pm0);
            }
            if (!sl1) { v10 = acc[mi][ni][2] * c0 * rv1; v11 = acc[mi][ni][3] * c1 * rv1; }
            else {
                v10 = acc[mi][ni][2] * 0.0625f * expf(e_r[t0 + cidx]     - pm1);
                v11 = acc[mi][ni][3] * 0.0625f * expf(e_r[t0 + cidx + 1] - pm1);
            }
            if (diag) {
                if (cidx     > r0)     v00 = 0.f;
                if (cidx + 1 > r0)     v01 = 0.f;
                if (cidx     > r0 + 8) v10 = 0.f;
                if (cidx + 1 > r0 + 8) v11 = 0.f;
            }
            sum0 += v00 + v01;
            sum1 += v10 + v11;
            float2 w0 = {tf32r(v00), tf32r(v01)};
            float2 w1 = {tf32r(v10), tf32r(v11)};
            *(float2*)(Cp + (long)(s0 + r0)     * Ss + t0 + cidx) = w0;
            *(float2*)(Cp + (long)(s0 + r0 + 8) * Ss + t0 + cidx) = w1;
        }
        sum0 += __shfl_xor_sync(0xffffffffu, sum0, 1);
        sum0 += __shfl_xor_sync(0xffffffffu, sum0, 2);
        sum1 += __shfl_xor_sync(0xffffffffu, sum1, 1);
        sum1 += __shfl_xor_sync(0xffffffffu, sum1, 2);
        if (tig == 0) {
            atomicAdd(&nsum[(long)z * Ss + s0 + r0], sum0);
            atomicAdd(&nsum[(long)z * Ss + s0 + r0 + 8], sum1);
        }
    }
}

// ---------------- prep: tf32-round all operands + zero g_n ------------------
__global__ void prep_all(const float* __restrict__ x, const float* __restrict__ Wi,
                         const float* __restrict__ Wu, const float* __restrict__ Wd) {
    const int n1 = ROWS * FIN / 4, n2 = Ee * FIN / 4,
              n3 = 2 * INNER * Ee / 4, n4 = Ee * INNER / 4, n5 = BNH * Ss / 4;
    int i = blockIdx.x * 256 + threadIdx.x;
    const float4* src; float4* dst; int j = i;
    if (j < n1)            { src = (const float4*)x;  dst = (float4*)g_xr; }
    else if ((j -= n1) < n2) { src = (const float4*)Wi; dst = (float4*)g_Wi; }
    else if ((j -= n2) < n3) { src = (const float4*)Wu; dst = (float4*)g_Wu; }
    else if ((j -= n3) < n4) { src = (const float4*)Wd; dst = (float4*)g_Wd; }
    else if ((j -= n4) < n5) { ((float4*)g_n)[j] = make_float4(0, 0, 0, 0); return; }
    else return;
    float4 v = src[j];
    v.x = tf32r(v.x); v.y = tf32r(v.y); v.z = tf32r(v.z); v.w = tf32r(v.w);
    dst[j] = v;
}

// ---------------- row LayerNorm; RND=1 rounds output to tf32 ---------------
template<int RND>
__global__ void ln_rows(const float* __restrict__ in, const float* __restrict__ w,
                        float* __restrict__ out, int W) {
    long row = blockIdx.x;
    const float* p = in + row * (long)W;
    float s = 0.f, s2 = 0.f;
    for (int j = threadIdx.x; j < W; j += blockDim.x) { float v = p[j]; s += v; s2 += v * v; }
    s  = blockReduceSum(s);
    s2 = blockReduceSum(s2);
    float mu  = s / W;
    float var = s2 / W - mu * mu;
    float r = rsqrtf(var + 1e-5f);
    for (int j = threadIdx.x; j < W; j += blockDim.x) {
        float o = (p[j] - mu) * r * w[j];
        out[row * (long)W + j] = RND ? tf32r(o) : o;
    }
}

// ---------------- fused conv+SiLU+headwise+GATES (row-local) ----------------
__global__ void __launch_bounds__(256)
conv_head(const float* __restrict__ cw, const float* __restrict__ cb,
          const float* __restrict__ Wq, const float* __restrict__ Wk,
          const float* __restrict__ Wv,
          const float* __restrict__ Wig, const float* __restrict__ big,
          const float* __restrict__ Wfg, const float* __restrict__ bfg) {
    __shared__ float xc_s[INNER];
    __shared__ float gsh[8][8];
    long row = blockIdx.x;
    int  t   = (int)(row & (Ss - 1));
    int tid = threadIdx.x, lane = tid & 31, wid = tid >> 5;
    #pragma unroll
    for (int l = 0; l < 4; ++l) {
        int c = tid + l * 256;
        float acc = cb[c];
        #pragma unroll
        for (int j = 0; j < KSk; ++j) {
            int dt = j - (KSk - 1);
            if (t + dt >= 0)
                acc += g_up[(row + dt) * (2 * INNER) + c] * cw[c * KSk + j];
        }
        float s = acc / (1.f + expf(-acc));
        xc_s[c] = s;
        g_xc[row * INNER + c] = s;
    }
    __syncthreads();
    int nb = tid;
    long base = row * INNER + nb * 4;
    float4 xm = *(const float4*)&g_up[row * (2 * INNER) + nb * 4];
    float xc4[4] = {xc_s[nb * 4], xc_s[nb * 4 + 1], xc_s[nb * 4 + 2], xc_s[nb * 4 + 3]};
    float xm4[4] = {xm.x, xm.y, xm.z, xm.w};
    float qr[4], kr[4], vr[4], qo[4], ko[4], vo[4];
    #pragma unroll
    for (int o = 0; o < 4; ++o) {
        float q = 0.f, k = 0.f, v = 0.f;
        #pragma unroll
        for (int i = 0; i < 4; ++i) {
            q += xc4[i] * Wq[nb * 16 + o * 4 + i];
            k += xc4[i] * Wk[nb * 16 + o * 4 + i];
            v += xm4[i] * Wv[nb * 16 + o * 4 + i];
        }
        qr[o] = q; kr[o] = k; vr[o] = v;
        qo[o] = tf32r(q); ko[o] = tf32r(k); vo[o] = tf32r(v);
    }
    *(float4*)&g_q[base] = *(float4*)qo;
    *(float4*)&g_k[base] = *(float4*)ko;
    *(float4*)&g_v[base] = *(float4*)vo;

    // --- fused gate projections: red[0..3]=ig heads, red[4..7]=fg heads ---
    float red[8];
    #pragma unroll
    for (int n = 0; n < 4; ++n) {
        const float* wi = Wig + (long)n * 3 * INNER;
        const float* wf = Wfg + (long)n * 3 * INNER;
        float ai = 0.f, af = 0.f;
        #pragma unroll
        for (int o = 0; o < 4; ++o) {
            int c = nb * 4 + o;
            ai += qr[o] * wi[c] + kr[o] * wi[INNER + c] + vr[o] * wi[2 * INNER + c];
            af += qr[o] * wf[c] + kr[o] * wf[INNER + c] + vr[o] * wf[2 * INNER + c];
        }
        red[n] = ai; red[4 + n] = af;
    }
    #pragma unroll
    for (int v = 0; v < 8; ++v) {
        #pragma unroll
        for (int o = 16; o; o >>= 1)
            red[v] += __shfl_down_sync(0xffffffffu, red[v], o);
    }
    if (lane == 0) {
        #pragma unroll
        for (int v = 0; v < 8; ++v) gsh[wid][v] = red[v];
    }
    __syncthreads();
    if (tid < 8) {
        float s = 0.f;
        #pragma unroll
        for (int w = 0; w < 8; ++w) s += gsh[w][tid];
        int b = (int)(row >> 10), ss = (int)(row & 1023);
        if (tid < 4) g_ig[(b * NHh + tid) * Ss + ss] = s + big[tid];
        else         g_fg[(b * NHh + tid - 4) * Ss + ss] = s + bfg[tid - 4];
    }
}

// ---------------- per-head v transpose --------------------------------------
__global__ void transpose_v() {
    __shared__ float t[32][33];
    int bn = blockIdx.z;
    int s0 = blockIdx.x * 32, d0 = blockIdx.y * 32;
    int tx = threadIdx.x, ty = threadIdx.y;
    t[ty][tx] = g_v[((long)(bn >> 2) * Ss + s0 + ty) * INNER + (bn & 3) * DHd + d0 + tx];
    __syncthreads();
    g_vT[((long)bn * DHd + d0 + ty) * Ss + s0 + tx] = t[tx][ty];
}

// ---------------- parallel gate scan (one block per bn, 1024 threads) -------
__global__ void __launch_bounds__(1024)
gate_scan_par() {
    __shared__ float wsum[32];
    int bn = blockIdx.x;
    int t = threadIdx.x, lane = t & 31, wid = t >> 5;
    float f  = g_fg[bn * Ss + t];
    float lf = fminf(f, 0.f) - log1pf(expf(-fabsf(f)));   // log_sigmoid

    float v = lf;
    #pragma unroll
    for (int o = 1; o < 32; o <<= 1) {
        float nv = __shfl_up_sync(0xffffffffu, v, o);
        if (lane >= o) v += nv;
    }
    if (lane == 31) wsum[wid] = v;
    __syncthreads();
    if (wid == 0) {
        float w = wsum[lane];
        #pragma unroll
        for (int o = 1; o < 32; o <<= 1) {
            float nv = __shfl_up_sync(0xffffffffu, w, o);
            if (lane >= o) w += nv;
        }
        wsum[lane] = w;
    }
    __syncthreads();
    float a = v + (wid > 0 ? wsum[wid - 1] : 0.f);

    float e = g_ig[bn * Ss + t] - a;
    __syncthreads();

    float m = e;
    #pragma unroll
    for (int o = 1; o < 32; o <<= 1) {
        float nv = __shfl_up_sync(0xffffffffu, m, o);
        if (lane >= o) m = fmaxf(m, nv);
    }
    if (lane == 31) wsum[wid] = m;
    __syncthreads();
    if (wid == 0) {
        float w = wsum[lane];
        #pragma unroll
        for (int o = 1; o < 32; o <<= 1) {
            float nv = __shfl_up_sync(0xffffffffu, w, o);
            if (lane >= o) w = fmaxf(w, nv);
        }
        wsum[lane] = w;
    }
    __syncthreads();
    float pm = (wid > 0) ? fmaxf(m, wsum[wid - 1]) : m;

    g_e [bn * Ss + t] = e;
    g_pm[bn * Ss + t] = pm;
    g_md[bn * Ss + t] = a + pm;
}

// ---------------- per-head LN + 1/n + skip + SiLU(z) gate -------------------
__global__ void mhln_combine(const float* __restrict__ mw, const float* __restrict__ skip) {
    int s  = blockIdx.x;
    int bn = blockIdx.y;
    int b = bn >> 2, n = bn & 3;
    int d = threadIdx.x;
    float rs = g_n[bn * Ss + s];
    float nn = fmaxf(fabsf(rs), expf(-g_md[bn * Ss + s]));
    float inv = 1.f / (nn + 1e-6f);
    size_t hrow = ((size_t)bn * Ss + s) * DHd;
    float x  = g_hh[hrow + d] * inv;
    float su = blockReduceSum(x);
    float s2 = blockReduceSum(x * x);
    float mu  = su / DHd;
    float var = s2 / DHd - mu * mu;
    float hn = (x - mu) * rsqrtf(var + 1e-5f) * mw[n * DHd + d];
    int c = n * DHd + d;
    size_t row = (size_t)(b * Ss + s);
    float xc = g_xc[row * INNER + c];
    float z  = g_up[row * (2 * INNER) + INNER + c];
    float sz = z / (1.f + expf(-z));
    g_hs[row * INNER + c] = tf32r((hn + skip[c] * xc) * sz);
}

// ---------------- out = LN(res + y) -> d_out --------------------------------
__global__ void add_ln_out(const float* __restrict__ w, float* __restrict__ out) {
    long row = blockIdx.x;
    float vals[2];
    float s = 0.f, s2 = 0.f;
    #pragma unroll
    for (int l = 0; l < 2; ++l) {
        int j = threadIdx.x + l * 256;
        float v = g_xp[row * Ee + j] + g_y[row * Ee + j];
        vals[l] = v; s += v; s2 += v * v;
    }
    s  = blockReduceSum(s);
    s2 = blockReduceSum(s2);
    float mu  = s / Ee;
    float var = s2 / Ee - mu * mu;
    float r = rsqrtf(var + 1e-5f);
    #pragma unroll
    for (int l = 0; l < 2; ++l) {
        int j = threadIdx.x + l * 256;
        out[row * Ee + j] = (vals[l] - mu) * r * w[j];
    }
}

// ---------------- launch ----------------------------------------------------
extern "C" void kernel_launch(void* const* d_in, const int* /*in_sizes*/, int /*n_in*/,
                              void* d_out, int /*out_size*/) {
    const float* x         = (const float*)d_in[0];
    const float* W_in      = (const float*)d_in[1];
    const float* b_in      = (const float*)d_in[2];
    const float* ln1_w     = (const float*)d_in[3];
    const float* W_up      = (const float*)d_in[4];
    const float* conv_w    = (const float*)d_in[5];
    const float* conv_b    = (const float*)d_in[6];
    const float* Wq        = (const float*)d_in[7];
    const float* Wk        = (const float*)d_in[8];
    const float* Wv        = (const float*)d_in[9];
    const float* W_ig      = (const float*)d_in[10];
    const float* b_ig      = (const float*)d_in[11];
    const float* W_fg      = (const float*)d_in[12];
    const float* b_fg      = (const float*)d_in[13];
    const float* mhln_w    = (const float*)d_in[14];
    const float* skip      = (const float*)d_in[15];
    const float* W_down    = (const float*)d_in[16];
    const float* ln_post_w = (const float*)d_in[17];
    float* out = (float*)d_out;

    void *pxp, *ph, *pup, *pq, *pk, *pvT, *pC, *phh, *phs, *py;
    void *pxr, *pWi, *pWu, *pWd, *pe, *ppm, *pn;
    cudaGetSymbolAddress(&pxp, g_xp);
    cudaGetSymbolAddress(&ph,  g_h);
    cudaGetSymbolAddress(&pup, g_up);
    cudaGetSymbolAddress(&pq,  g_q);
    cudaGetSymbolAddress(&pk,  g_k);
    cudaGetSymbolAddress(&pvT, g_vT);
    cudaGetSymbolAddress(&pC,  g_C);
    cudaGetSymbolAddress(&phh, g_hh);
    cudaGetSymbolAddress(&phs, g_hs);
    cudaGetSymbolAddress(&py,  g_y);
    cudaGetSymbolAddress(&pxr, g_xr);
    cudaGetSymbolAddress(&pWi, g_Wi);
    cudaGetSymbolAddress(&pWu, g_Wu);
    cudaGetSymbolAddress(&pWd, g_Wd);
    cudaGetSymbolAddress(&pe,  g_e);
    cudaGetSymbolAddress(&ppm, g_pm);
    cudaGetSymbolAddress(&pn,  g_n);

    cudaFuncSetAttribute(mma_gemm<0>, cudaFuncAttributeMaxDynamicSharedMemorySize, GSMEM);
    cudaFuncSetAttribute(mma_gemm<2>, cudaFuncAttributeMaxDynamicSharedMemorySize, GSMEM);
    cudaFuncSetAttribute(qk_fused,    cudaFuncAttributeMaxDynamicSharedMemorySize, QKSMEM);

    // 0. prep: tf32-round operands, zero g_n
    {
        int total = ROWS * FIN / 4 + Ee * FIN / 4 + 2 * INNER * Ee / 4
                  + Ee * INNER / 4 + BNH * Ss / 4;
        prep_all<<<(total + 255) / 256, 256>>>(x, W_in, W_up, W_down);
    }

    // 1. xp = x @ W_in^T + b_in
    mma_gemm<0><<<dim3(Ee / 128, ROWS / 128, 1), 256, GSMEM>>>(
        (const float*)pxr, (const float*)pWi, (float*)pxp, b_in,
        FIN, FIN, FIN, Ee, 0, 0, 0, 0, 0, 0);

    // 2. h = LN(xp), tf32
    ln_rows<1><<<ROWS, 256>>>((const float*)pxp, ln1_w, (float*)ph, Ee);

    // 3. up = h @ W_up^T
    mma_gemm<0><<<dim3(2 * INNER / 128, ROWS / 128, 1), 256, GSMEM>>>(
        (const float*)ph, (const float*)pWu, (float*)pup, nullptr,
        Ee, Ee, Ee, 2 * INNER, 0, 0, 0, 0, 0, 0);

    // 4. fused conv+SiLU+headwise+gates
    conv_head<<<ROWS, 256>>>(conv_w, conv_b, Wq, Wk, Wv, W_ig, b_ig, W_fg, b_fg);

    // 5. parallel gate scan
    gate_scan_par<<<BNH, 1024>>>();

    // 5b. v transpose
    transpose_v<<<dim3(Ss / 32, DHd / 32, BNH), dim3(32, 32)>>>();

    // 6. fused QK^T * decay + rowsum
    qk_fused<<<dim3(Ss / 128, Ss / 128, BNH), 256, QKSMEM>>>(
        (const float*)pq, (const float*)pk, (float*)pC,
        (const float*)pe, (const float*)ppm, (float*)pn);

    // 7. hh = C @ vT^T per head (K limited to causal extent)
    mma_gemm<2><<<dim3(DHd / 128, Ss / 128, BNH), 256, GSMEM>>>(
        (const float*)pC, (const float*)pvT, (float*)phh, nullptr,
        Ss, Ss, Ss, DHd,
        4L * Ss * Ss, (long)Ss * Ss,
        4L * DHd * Ss, (long)DHd * Ss,
        4L * Ss * DHd, (long)Ss * DHd);

    // 8. per-head LN + 1/n + combine
    mhln_combine<<<dim3(Ss, BNH), 256>>>(mhln_w, skip);

    // 9. y = h_state @ W_down^T
    mma_gemm<0><<<dim3(Ee / 128, ROWS / 128, 1), 256, GSMEM>>>(
        (const float*)phs, (const float*)pWd, (float*)py, nullptr,
        INNER, INNER, INNER, Ee, 0, 0, 0, 0, 0, 0);

    // 10. out = LN(res + y)
    add_ln_out<<<ROWS, 256>>>(ln_post_w, out);
}

// round 12
// speedup vs baseline: 1.5166x; 1.1458x over previous
#include <cuda_runtime.h>
#include <cstdint>
#include <math.h>

// ---------------- problem constants ----------------
namespace {
constexpr int Bb    = 8;
constexpr int Ss    = 1024;
constexpr int FIN   = 256;
constexpr int Ee    = 512;
constexpr int INNER = 1024;
constexpr int NHh   = 4;
constexpr int DHd   = 256;
constexpr int KSk   = 4;
constexpr int ROWS  = Bb * Ss;      // 8192
constexpr int BNH   = Bb * NHh;     // 32

// smem tile geometry (512 threads, 16 warps: 4x4 grid, 32x32 per warp)
constexpr int KT      = 32;
constexpr int ROWSTR  = 36;
constexpr int TILE_F  = 128 * ROWSTR;        // 4608
constexpr int STAGE_F = 2 * TILE_F;          // 9216
constexpr int NSTAGE  = 3;
constexpr int GSMEM   = NSTAGE * STAGE_F * 4;          // 110592
constexpr int QKSMEM  = GSMEM + 3 * 128 * 4;           // +cf/rf/rfl
constexpr int NTHR    = 512;
}

// ---------------- scratch ----------------
__device__ float g_xp[(size_t)ROWS * Ee];
__device__ float g_h [(size_t)ROWS * Ee];
__device__ float g_up[(size_t)ROWS * 2 * INNER];
__device__ float g_xc[(size_t)ROWS * INNER];
__device__ float g_q [(size_t)ROWS * INNER];
__device__ float g_k [(size_t)ROWS * INNER];
__device__ float g_v [(size_t)ROWS * INNER];
__device__ float g_vT[(size_t)BNH * DHd * Ss];
__device__ float g_ig[BNH * Ss];
__device__ float g_fg[BNH * Ss];
__device__ float g_e [BNH * Ss];
__device__ float g_pm[BNH * Ss];
__device__ float g_md[BNH * Ss];
__device__ float g_n [BNH * Ss];
__device__ float g_C [(size_t)BNH * Ss * Ss];
__device__ float g_hh[(size_t)BNH * Ss * DHd];
__device__ float g_hs[(size_t)ROWS * INNER];
__device__ float g_y [(size_t)ROWS * Ee];
__device__ float g_xr[(size_t)ROWS * FIN];
__device__ float g_Wi[(size_t)Ee * FIN];
__device__ float g_Wu[(size_t)2 * INNER * Ee];
__device__ float g_Wd[(size_t)Ee * INNER];

// ---------------- helpers ----------------
__device__ __forceinline__ float tf32r(float x) {
    uint32_t u;
    asm("cvt.rna.tf32.f32 %0, %1;" : "=r"(u) : "f"(x));
    return __uint_as_float(u);
}
__device__ __forceinline__ void mma_tf32(float* c, const uint32_t* a, const uint32_t* b) {
    asm volatile(
        "mma.sync.aligned.m16n8k8.row.col.f32.tf32.tf32.f32 "
        "{%0,%1,%2,%3}, {%4,%5,%6,%7}, {%8,%9}, {%0,%1,%2,%3};"
        : "+f"(c[0]), "+f"(c[1]), "+f"(c[2]), "+f"(c[3])
        : "r"(a[0]), "r"(a[1]), "r"(a[2]), "r"(a[3]), "r"(b[0]), "r"(b[1]));
}
__device__ __forceinline__ uint32_t smem_u32(const void* p) {
    uint32_t a;
    asm("{ .reg .u64 t; cvta.to.shared.u64 t, %1; cvt.u32.u64 %0, t; }" : "=r"(a) : "l"(p));
    return a;
}
#define CP16(dst, src) \
    asm volatile("cp.async.cg.shared.global [%0], [%1], 16;" :: "r"(dst), "l"(src) : "memory")
#define CP_COMMIT() asm volatile("cp.async.commit_group;" ::: "memory")
#define CP_WAIT(n)  asm volatile("cp.async.wait_group %0;" :: "n"(n) : "memory")

__device__ __forceinline__ float blockReduceSum(float v) {
    __shared__ float sh[33];
    int lane = threadIdx.x & 31, wid = threadIdx.x >> 5;
    #pragma unroll
    for (int o = 16; o; o >>= 1) v += __shfl_down_sync(0xffffffffu, v, o);
    if (lane == 0) sh[wid] = v;
    __syncthreads();
    int nw = blockDim.x >> 5;
    float t = (threadIdx.x < nw) ? sh[threadIdx.x] : 0.f;
    if (wid == 0) {
        #pragma unroll
        for (int o = 16; o; o >>= 1) t += __shfl_down_sync(0xffffffffu, t, o);
        if (lane == 0) sh[32] = t;
    }
    __syncthreads();
    float r = sh[32];
    __syncthreads();
    return r;
}

// ---------------- GEMM machinery (512 threads, 4x4 warps, 32x32/warp) -------
__device__ __forceinline__ void g_load_tile(uint32_t sb, int stage,
                                            const float* A, const float* B,
                                            int kt, int lda, int ldb) {
    int lrow = threadIdx.x >> 2;          // 0..127
    int lch  = (threadIdx.x & 3) * 2;     // chunk pair {lch, lch+1} of 8
    uint32_t abase = sb + (uint32_t)(stage * STAGE_F) * 4 + lrow * (ROWSTR * 4);
    uint32_t bbase = abase + TILE_F * 4;
    const float* ap = A + (long)lrow * lda + kt * KT + lch * 4;
    const float* bp = B + (long)lrow * ldb + kt * KT + lch * 4;
    #pragma unroll
    for (int i = 0; i < 2; ++i) {
        CP16(abase + (lch + i) * 16, ap + i * 4);
        CP16(bbase + (lch + i) * 16, bp + i * 4);
    }
}

__device__ __forceinline__ void g_compute_tile(const float* As, const float* Bs,
                                               int wm, int wn, int gid, int tig,
                                               float acc[2][4][4]) {
    #pragma unroll
    for (int ks = 0; ks < 4; ++ks) {
        int kc = ks * 8;
        uint32_t a[2][4], b[4][2];
        #pragma unroll
        for (int mi = 0; mi < 2; ++mi) {
            int r = wm * 32 + mi * 16 + gid;
            a[mi][0] = __float_as_uint(As[r * ROWSTR + kc + tig]);
            a[mi][1] = __float_as_uint(As[(r + 8) * ROWSTR + kc + tig]);
            a[mi][2] = __float_as_uint(As[r * ROWSTR + kc + tig + 4]);
            a[mi][3] = __float_as_uint(As[(r + 8) * ROWSTR + kc + tig + 4]);
        }
        #pragma unroll
        for (int ni = 0; ni < 4; ++ni) {
            int n = wn * 32 + ni * 8 + gid;
            b[ni][0] = __float_as_uint(Bs[n * ROWSTR + kc + tig]);
            b[ni][1] = __float_as_uint(Bs[n * ROWSTR + kc + tig + 4]);
        }
        #pragma unroll
        for (int mi = 0; mi < 2; ++mi)
            #pragma unroll
            for (int ni = 0; ni < 4; ++ni)
                mma_tf32(acc[mi][ni], a[mi], b[ni]);
    }
}

// 3-stage mainloop (R7-proven): one __syncthreads per K-tile; CP_WAIT(1)
// keeps one group in flight; load(kt+2) overlaps compute(kt).
#define GEMM_MAINLOOP(Aptr, Bptr, LDA, LDB)                                  \
    g_load_tile(sb, 0, Aptr, Bptr, 0, LDA, LDB);                             \
    CP_COMMIT();                                                             \
    if (nT > 1) { g_load_tile(sb, 1, Aptr, Bptr, 1, LDA, LDB); CP_COMMIT(); }\
    for (int kt = 0; kt < nT; ++kt) {                                        \
        if (kt + 1 < nT) { CP_WAIT(1); } else { CP_WAIT(0); }                \
        __syncthreads();                                                     \
        int nx = kt + 2;                                                     \
        if (nx < nT) { g_load_tile(sb, nx % 3, Aptr, Bptr, nx, LDA, LDB);    \
                       CP_COMMIT(); }                                        \
        g_compute_tile(sm + (kt % 3) * STAGE_F,                              \
                       sm + (kt % 3) * STAGE_F + TILE_F,                     \
                       wm, wn, gid, tig, acc);                               \
    }

// ---------------- general GEMM: C = A(M,K) * B(N,K)^T [+bias] --------------
template<int TRI>   // TRI=0 full, TRI=2 K limited to (by+1)*128
__global__ void __launch_bounds__(NTHR, 2)
mma_gemm(const float* __restrict__ Ag, const float* __restrict__ Bg,
         float* __restrict__ Cg, const float* __restrict__ bias,
         int K, int lda, int ldb, int ldc,
         long aOffB, long aOffN, long bOffB, long bOffN, long cOffB, long cOffN) {
    int bx = blockIdx.x, by = blockIdx.y, z = blockIdx.z;
    extern __shared__ float sm[];
    uint32_t sb = smem_u32(sm);
    const float* A = Ag + (long)(z >> 2) * aOffB + (long)(z & 3) * aOffN + (long)by * 128 * lda;
    const float* B = Bg + (long)(z >> 2) * bOffB + (long)(z & 3) * bOffN + (long)bx * 128 * ldb;
    float*       Cp = Cg + (long)(z >> 2) * cOffB + (long)(z & 3) * cOffN;

    int Keff = (TRI == 2) ? min(K, (by + 1) * 128) : K;
    int nT = Keff / KT;

    int tid = threadIdx.x, wid = tid >> 5, lane = tid & 31;
    int wm = wid >> 2, wn = wid & 3;
    int gid = lane >> 2, tig = lane & 3;

    float acc[2][4][4] = {};
    GEMM_MAINLOOP(A, B, lda, ldb)

    long m0 = (long)by * 128 + wm * 32;
    long n0 = (long)bx * 128 + wn * 32;
    #pragma unroll
    for (int mi = 0; mi < 2; ++mi) {
        #pragma unroll
        for (int ni = 0; ni < 4; ++ni) {
            long r = m0 + mi * 16 + gid;
            long c = n0 + ni * 8 + tig * 2;
            float b0 = bias ? bias[c] : 0.f, b1 = bias ? bias[c + 1] : 0.f;
            float2 v0 = {acc[mi][ni][0] + b0, acc[mi][ni][1] + b1};
            float2 v1 = {acc[mi][ni][2] + b0, acc[mi][ni][3] + b1};
            *(float2*)(Cp + r * ldc + c) = v0;
            *(float2*)(Cp + (r + 8) * ldc + c) = v1;
        }
    }
}

// ---------------- fused QK^T + decay + mask + rowsum ------------------------
__global__ void __launch_bounds__(NTHR, 2)
qk_fused(const float* __restrict__ qg, const float* __restrict__ kg,
         float* __restrict__ Cg, const float* __restrict__ eg,
         const float* __restrict__ pmg, float* __restrict__ nsum) {
    int bx = blockIdx.x, by = blockIdx.y, z = blockIdx.z;
    if (bx > by) return;
    extern __shared__ float sm[];
    uint32_t sb = smem_u32(sm);
    int tid = threadIdx.x, wid = tid >> 5, lane = tid & 31;
    int wm = wid >> 2, wn = wid & 3;
    int gid = lane >> 2, tig = lane & 3;

    const float* A = qg + (long)(z >> 2) * Ss * INNER + (long)(z & 3) * DHd + (long)by * 128 * INNER;
    const float* B = kg + (long)(z >> 2) * Ss * INNER + (long)(z & 3) * DHd + (long)bx * 128 * INNER;
    float* Cp = Cg + (long)z * Ss * Ss;
    const float* e_r  = eg  + (long)z * Ss;
    const float* pm_r = pmg + (long)z * Ss;
    int s0 = by * 128, t0 = bx * 128;
    float P = pm_r[s0 + 127];

    float* cf  = sm + NSTAGE * STAGE_F;
    float* rf  = cf + 128;
    float* rfl = rf + 128;
    if (tid < 128) {
        int j = tid;
        cf[j] = expf(e_r[t0 + j] - P) * 0.0625f;
        float rl = P - pm_r[s0 + j];
        rfl[j] = rl;
        rf[j] = expf(fminf(rl, 60.f));
    }

    float acc[2][4][4] = {};
    const int nT = DHd / KT;   // 8
    GEMM_MAINLOOP(A, B, INNER, INNER)

    bool diag = (bx == by);
    #pragma unroll
    for (int mi = 0; mi < 2; ++mi) {
        int r0 = wm * 32 + mi * 16 + gid;
        float rl0 = rfl[r0], rl1 = rfl[r0 + 8];
        bool  sl0 = rl0 > 60.f, sl1 = rl1 > 60.f;
        float rv0 = rf[r0], rv1 = rf[r0 + 8];
        float pm0 = P - rl0, pm1 = P - rl1;
        float sum0 = 0.f, sum1 = 0.f;
        #pragma unroll
        for (int ni = 0; ni < 4; ++ni) {
            int cidx = wn * 32 + ni * 8 + tig * 2;
            float c0 = cf[cidx], c1 = cf[cidx + 1];
            float v00, v01, v10, v11;
            if (!sl0) { v00 = acc[mi][ni][0] * c0 * rv0; v01 = acc[mi][ni][1] * c1 * rv0; }
            else {
                v00 = acc[mi][ni][0] * 0.0625f * expf(e_r[t0 + cidx]     - pm0);
                v01 = acc[mi][ni][1] * 0.0625f * expf(e_r[t0 + cidx + 1] - pm0);
            }
            if (!sl1) { v10 = acc[mi][ni][2] * c0 * rv1; v11 = acc[mi][ni][3] * c1 * rv1; }
            else {
                v10 = acc[mi][ni][2] * 0.0625f * expf(e_r[t0 + cidx]     - pm1);
                v11 = acc[mi][ni][3] * 0.0625f * expf(e_r[t0 + cidx + 1] - pm1);
            }
            if (diag) {
                if (cidx     > r0)     v00 = 0.f;
                if (cidx + 1 > r0)     v01 = 0.f;
                if (cidx     > r0 + 8) v10 = 0.f;
                if (cidx + 1 > r0 + 8) v11 = 0.f;
            }
            sum0 += v00 + v01;
            sum1 += v10 + v11;
            float2 w0 = {tf32r(v00), tf32r(v01)};
            float2 w1 = {tf32r(v10), tf32r(v11)};
            *(float2*)(Cp + (long)(s0 + r0)     * Ss + t0 + cidx) = w0;
            *(float2*)(Cp + (long)(s0 + r0 + 8) * Ss + t0 + cidx) = w1;
        }
        sum0 += __shfl_xor_sync(0xffffffffu, sum0, 1);
        sum0 += __shfl_xor_sync(0xffffffffu, sum0, 2);
        sum1 += __shfl_xor_sync(0xffffffffu, sum1, 1);
        sum1 += __shfl_xor_sync(0xffffffffu, sum1, 2);
        if (tig == 0) {
            atomicAdd(&nsum[(long)z * Ss + s0 + r0], sum0);
            atomicAdd(&nsum[(long)z * Ss + s0 + r0 + 8], sum1);
        }
    }
}

// ---------------- prep: tf32-round all operands + zero g_n ------------------
__global__ void prep_all(const float* __restrict__ x, const float* __restrict__ Wi,
                         const float* __restrict__ Wu, const float* __restrict__ Wd) {
    const int n1 = ROWS * FIN / 4, n2 = Ee * FIN / 4,
              n3 = 2 * INNER * Ee / 4, n4 = Ee * INNER / 4, n5 = BNH * Ss / 4;
    int i = blockIdx.x * 256 + threadIdx.x;
    const float4* src; float4* dst; int j = i;
    if (j < n1)            { src = (const float4*)x;  dst = (float4*)g_xr; }
    else if ((j -= n1) < n2) { src = (const float4*)Wi; dst = (float4*)g_Wi; }
    else if ((j -= n2) < n3) { src = (const float4*)Wu; dst = (float4*)g_Wu; }
    else if ((j -= n3) < n4) { src = (const float4*)Wd; dst = (float4*)g_Wd; }
    else if ((j -= n4) < n5) { ((float4*)g_n)[j] = make_float4(0, 0, 0, 0); return; }
    else return;
    float4 v = src[j];
    v.x = tf32r(v.x); v.y = tf32r(v.y); v.z = tf32r(v.z); v.w = tf32r(v.w);
    dst[j] = v;
}

// ---------------- row LayerNorm; RND=1 rounds output to tf32 ---------------
template<int RND>
__global__ void ln_rows(const float* __restrict__ in, const float* __restrict__ w,
                        float* __restrict__ out, int W) {
    long row = blockIdx.x;
    const float* p = in + row * (long)W;
    float s = 0.f, s2 = 0.f;
    for (int j = threadIdx.x; j < W; j += blockDim.x) { float v = p[j]; s += v; s2 += v * v; }
    s  = blockReduceSum(s);
    s2 = blockReduceSum(s2);
    float mu  = s / W;
    float var = s2 / W - mu * mu;
    float r = rsqrtf(var + 1e-5f);
    for (int j = threadIdx.x; j < W; j += blockDim.x) {
        float o = (p[j] - mu) * r * w[j];
        out[row * (long)W + j] = RND ? tf32r(o) : o;
    }
}

// ---------------- fused conv+SiLU+headwise (R7 version) ---------------------
__global__ void __launch_bounds__(256)
conv_head(const float* __restrict__ cw, const float* __restrict__ cb,
          const float* __restrict__ Wq, const float* __restrict__ Wk,
          const float* __restrict__ Wv) {
    __shared__ float xc_s[INNER];
    long row = blockIdx.x;
    int  t   = (int)(row & (Ss - 1));
    int tid = threadIdx.x;
    #pragma unroll
    for (int l = 0; l < 4; ++l) {
        int c = tid + l * 256;
        float acc = cb[c];
        #pragma unroll
        for (int j = 0; j < KSk; ++j) {
            int dt = j - (KSk - 1);
            if (t + dt >= 0)
                acc += g_up[(row + dt) * (2 * INNER) + c] * cw[c * KSk + j];
        }
        float s = acc / (1.f + expf(-acc));
        xc_s[c] = s;
        g_xc[row * INNER + c] = s;
    }
    __syncthreads();
    int nb = tid;
    long base = row * INNER + nb * 4;
    float4 xm = *(const float4*)&g_up[row * (2 * INNER) + nb * 4];
    float xc4[4] = {xc_s[nb * 4], xc_s[nb * 4 + 1], xc_s[nb * 4 + 2], xc_s[nb * 4 + 3]};
    float xm4[4] = {xm.x, xm.y, xm.z, xm.w};
    float qo[4], ko[4], vo[4];
    #pragma unroll
    for (int o = 0; o < 4; ++o) {
        float q = 0.f, k = 0.f, v = 0.f;
        #pragma unroll
        for (int i = 0; i < 4; ++i) {
            q += xc4[i] * Wq[nb * 16 + o * 4 + i];
            k += xc4[i] * Wk[nb * 16 + o * 4 + i];
            v += xm4[i] * Wv[nb * 16 + o * 4 + i];
        }
        qo[o] = tf32r(q); ko[o] = tf32r(k); vo[o] = tf32r(v);
    }
    *(float4*)&g_q[base] = *(float4*)qo;
    *(float4*)&g_k[base] = *(float4*)ko;
    *(float4*)&g_v[base] = *(float4*)vo;
}

// ---------------- per-head v transpose --------------------------------------
__global__ void transpose_v() {
    __shared__ float t[32][33];
    int bn = blockIdx.z;
    int s0 = blockIdx.x * 32, d0 = blockIdx.y * 32;
    int tx = threadIdx.x, ty = threadIdx.y;
    t[ty][tx] = g_v[((long)(bn >> 2) * Ss + s0 + ty) * INNER + (bn & 3) * DHd + d0 + tx];
    __syncthreads();
    g_vT[((long)bn * DHd + d0 + ty) * Ss + s0 + tx] = t[tx][ty];
}

// ---------------- gate projections (R7 version) ------------------------------
__global__ void gates(const float* __restrict__ Wig, const float* __restrict__ big,
                      const float* __restrict__ Wfg, const float* __restrict__ bfg) {
    long row = blockIdx.x;
    float aI[4] = {0, 0, 0, 0}, aF[4] = {0, 0, 0, 0};
    for (int c = threadIdx.x; c < INNER; c += blockDim.x) {
        float qv = g_q[row * INNER + c];
        float kv = g_k[row * INNER + c];
        float vv = g_v[row * INNER + c];
        #pragma unroll
        for (int n = 0; n < 4; ++n) {
            const float* wi = Wig + (long)n * 3 * INNER;
            const float* wf = Wfg + (long)n * 3 * INNER;
            aI[n] += qv * wi[c] + kv * wi[INNER + c] + vv * wi[2 * INNER + c];
            aF[n] += qv * wf[c] + kv * wf[INNER + c] + vv * wf[2 * INNER + c];
        }
    }
    int b = (int)(row >> 10), s = (int)(row & 1023);
    #pragma unroll
    for (int n = 0; n < 4; ++n) {
        float si = blockReduceSum(aI[n]);
        float sf = blockReduceSum(aF[n]);
        if (threadIdx.x == 0) {
            g_ig[(b * NHh + n) * Ss + s] = si + big[n];
            g_fg[(b * NHh + n) * Ss + s] = sf + bfg[n];
        }
    }
}

// ---------------- parallel gate scan (one block per bn, 1024 threads) -------
__global__ void __launch_bounds__(1024)
gate_scan_par() {
    __shared__ float wsum[32];
    int bn = blockIdx.x;
    int t = threadIdx.x, lane = t & 31, wid = t >> 5;
    float f  = g_fg[bn * Ss + t];
    float lf = fminf(f, 0.f) - log1pf(expf(-fabsf(f)));   // log_sigmoid

    float v = lf;
    #pragma unroll
    for (int o = 1; o < 32; o <<= 1) {
        float nv = __shfl_up_sync(0xffffffffu, v, o);
        if (lane >= o) v += nv;
    }
    if (lane == 31) wsum[wid] = v;
    __syncthreads();
    if (wid == 0) {
        float w = wsum[lane];
        #pragma unroll
        for (int o = 1; o < 32; o <<= 1) {
            float nv = __shfl_up_sync(0xffffffffu, w, o);
            if (lane >= o) w += nv;
        }
        wsum[lane] = w;
    }
    __syncthreads();
    float a = v + (wid > 0 ? wsum[wid - 1] : 0.f);

    float e = g_ig[bn * Ss + t] - a;
    __syncthreads();

    float m = e;
    #pragma unroll
    for (int o = 1; o < 32; o <<= 1) {
        float nv = __shfl_up_sync(0xffffffffu, m, o);
        if (lane >= o) m = fmaxf(m, nv);
    }
    if (lane == 31) wsum[wid] = m;
    __syncthreads();
    if (wid == 0) {
        float w = wsum[lane];
        #pragma unroll
        for (int o = 1; o < 32; o <<= 1) {
            float nv = __shfl_up_sync(0xffffffffu, w, o);
            if (lane >= o) w = fmaxf(w, nv);
        }
        wsum[lane] = w;
    }
    __syncthreads();
    float pm = (wid > 0) ? fmaxf(m, wsum[wid - 1]) : m;

    g_e [bn * Ss + t] = e;
    g_pm[bn * Ss + t] = pm;
    g_md[bn * Ss + t] = a + pm;
}

// ---------------- per-head LN + 1/n + skip + SiLU(z) gate -------------------
__global__ void mhln_combine(const float* __restrict__ mw, const float* __restrict__ skip) {
    int s  = blockIdx.x;
    int bn = blockIdx.y;
    int b = bn >> 2, n = bn & 3;
    int d = threadIdx.x;
    float rs = g_n[bn * Ss + s];
    float nn = fmaxf(fabsf(rs), expf(-g_md[bn * Ss + s]));
    float inv = 1.f / (nn + 1e-6f);
    size_t hrow = ((size_t)bn * Ss + s) * DHd;
    float x  = g_hh[hrow + d] * inv;
    float su = blockReduceSum(x);
    float s2 = blockReduceSum(x * x);
    float mu  = su / DHd;
    float var = s2 / DHd - mu * mu;
    float hn = (x - mu) * rsqrtf(var + 1e-5f) * mw[n * DHd + d];
    int c = n * DHd + d;
    size_t row = (size_t)(b * Ss + s);
    float xc = g_xc[row * INNER + c];
    float z  = g_up[row * (2 * INNER) + INNER + c];
    float sz = z / (1.f + expf(-z));
    g_hs[row * INNER + c] = tf32r((hn + skip[c] * xc) * sz);
}

// ---------------- out = LN(res + y) -> d_out --------------------------------
__global__ void add_ln_out(const float* __restrict__ w, float* __restrict__ out) {
    long row = blockIdx.x;
    float vals[2];
    float s = 0.f, s2 = 0.f;
    #pragma unroll
    for (int l = 0; l < 2; ++l) {
        int j = threadIdx.x + l * 256;
        float v = g_xp[row * Ee + j] + g_y[row * Ee + j];
        vals[l] = v; s += v; s2 += v * v;
    }
    s  = blockReduceSum(s);
    s2 = blockReduceSum(s2);
    float mu  = s / Ee;
    float var = s2 / Ee - mu * mu;
    float r = rsqrtf(var + 1e-5f);
    #pragma unroll
    for (int l = 0; l < 2; ++l) {
        int j = threadIdx.x + l * 256;
        out[row * Ee + j] = (vals[l] - mu) * r * w[j];
    }
}

// ---------------- launch ----------------------------------------------------
extern "C" void kernel_launch(void* const* d_in, const int* /*in_sizes*/, int /*n_in*/,
                              void* d_out, int /*out_size*/) {
    const float* x         = (const float*)d_in[0];
    const float* W_in      = (const float*)d_in[1];
    const float* b_in      = (const float*)d_in[2];
    const float* ln1_w     = (const float*)d_in[3];
    const float* W_up      = (const float*)d_in[4];
    const float* conv_w    = (const float*)d_in[5];
    const float* conv_b    = (const float*)d_in[6];
    const float* Wq        = (const float*)d_in[7];
    const float* Wk        = (const float*)d_in[8];
    const float* Wv        = (const float*)d_in[9];
    const float* W_ig      = (const float*)d_in[10];
    const float* b_ig      = (const float*)d_in[11];
    const float* W_fg      = (const float*)d_in[12];
    const float* b_fg      = (const float*)d_in[13];
    const float* mhln_w    = (const float*)d_in[14];
    const float* skip      = (const float*)d_in[15];
    const float* W_down    = (const float*)d_in[16];
    const float* ln_post_w = (const float*)d_in[17];
    float* out = (float*)d_out;

    void *pxp, *ph, *pup, *pq, *pk, *pvT, *pC, *phh, *phs, *py;
    void *pxr, *pWi, *pWu, *pWd, *pe, *ppm, *pn;
    cudaGetSymbolAddress(&pxp, g_xp);
    cudaGetSymbolAddress(&ph,  g_h);
    cudaGetSymbolAddress(&pup, g_up);
    cudaGetSymbolAddress(&pq,  g_q);
    cudaGetSymbolAddress(&pk,  g_k);
    cudaGetSymbolAddress(&pvT, g_vT);
    cudaGetSymbolAddress(&pC,  g_C);
    cudaGetSymbolAddress(&phh, g_hh);
    cudaGetSymbolAddress(&phs, g_hs);
    cudaGetSymbolAddress(&py,  g_y);
    cudaGetSymbolAddress(&pxr, g_xr);
    cudaGetSymbolAddress(&pWi, g_Wi);
    cudaGetSymbolAddress(&pWu, g_Wu);
    cudaGetSymbolAddress(&pWd, g_Wd);
    cudaGetSymbolAddress(&pe,  g_e);
    cudaGetSymbolAddress(&ppm, g_pm);
    cudaGetSymbolAddress(&pn,  g_n);

    cudaFuncSetAttribute(mma_gemm<0>, cudaFuncAttributeMaxDynamicSharedMemorySize, GSMEM);
    cudaFuncSetAttribute(mma_gemm<2>, cudaFuncAttributeMaxDynamicSharedMemorySize, GSMEM);
    cudaFuncSetAttribute(qk_fused,    cudaFuncAttributeMaxDynamicSharedMemorySize, QKSMEM);

    // 0. prep: tf32-round operands, zero g_n
    {
        int total = ROWS * FIN / 4 + Ee * FIN / 4 + 2 * INNER * Ee / 4
                  + Ee * INNER / 4 + BNH * Ss / 4;
        prep_all<<<(total + 255) / 256, 256>>>(x, W_in, W_up, W_down);
    }

    // 1. xp = x @ W_in^T + b_in
    mma_gemm<0><<<dim3(Ee / 128, ROWS / 128, 1), NTHR, GSMEM>>>(
        (const float*)pxr, (const float*)pWi, (float*)pxp, b_in,
        FIN, FIN, FIN, Ee, 0, 0, 0, 0, 0, 0);

    // 2. h = LN(xp), tf32
    ln_rows<1><<<ROWS, 256>>>((const float*)pxp, ln1_w, (float*)ph, Ee);

    // 3. up = h @ W_up^T
    mma_gemm<0><<<dim3(2 * INNER / 128, ROWS / 128, 1), NTHR, GSMEM>>>(
        (const float*)ph, (const float*)pWu, (float*)pup, nullptr,
        Ee, Ee, Ee, 2 * INNER, 0, 0, 0, 0, 0, 0);

    // 4. fused conv+SiLU+headwise
    conv_head<<<ROWS, 256>>>(conv_w, conv_b, Wq, Wk, Wv);

    // 5. gates
    gates<<<ROWS, 256>>>(W_ig, b_ig, W_fg, b_fg);

    // 6. parallel gate scan
    gate_scan_par<<<BNH, 1024>>>();

    // 6b. v transpose
    transpose_v<<<dim3(Ss / 32, DHd / 32, BNH), dim3(32, 32)>>>();

    // 7. fused QK^T * decay + rowsum
    qk_fused<<<dim3(Ss / 128, Ss / 128, BNH), NTHR, QKSMEM>>>(
        (const float*)pq, (const float*)pk, (float*)pC,
        (const float*)pe, (const float*)ppm, (float*)pn);

    // 8. hh = C @ vT^T per head (K limited to causal extent)
    mma_gemm<2><<<dim3(DHd / 128, Ss / 128, BNH), NTHR, GSMEM>>>(
        (const float*)pC, (const float*)pvT, (float*)phh, nullptr,
        Ss, Ss, Ss, DHd,
        4L * Ss * Ss, (long)Ss * Ss,
        4L * DHd * Ss, (long)DHd * Ss,
        4L * Ss * DHd, (long)Ss * DHd);

    // 9. per-head LN + 1/n + combine
    mhln_combine<<<dim3(Ss, BNH), 256>>>(mhln_w, skip);

    // 10. y = h_state @ W_down^T
    mma_gemm<0><<<dim3(Ee / 128, ROWS / 128, 1), NTHR, GSMEM>>>(
        (const float*)phs, (const float*)pWd, (float*)py, nullptr,
        INNER, INNER, INNER, Ee, 0, 0, 0, 0, 0, 0);

    // 11. out = LN(res + y)
    add_ln_out<<<ROWS, 256>>>(ln_post_w, out);
}

// round 13
// speedup vs baseline: 1.5440x; 1.0181x over previous
#include <cuda_runtime.h>
#include <cstdint>
#include <math.h>

// ---------------- problem constants ----------------
namespace {
constexpr int Bb    = 8;
constexpr int Ss    = 1024;
constexpr int FIN   = 256;
constexpr int Ee    = 512;
constexpr int INNER = 1024;
constexpr int NHh   = 4;
constexpr int DHd   = 256;
constexpr int KSk   = 4;
constexpr int ROWS  = Bb * Ss;      // 8192
constexpr int BNH   = Bb * NHh;     // 32

// smem tile geometry (512 threads, 16 warps: 4x4 grid, 32x32 per warp)
constexpr int KT      = 32;
constexpr int ROWSTR  = 36;
constexpr int TILE_F  = 128 * ROWSTR;        // 4608
constexpr int STAGE_F = 2 * TILE_F;          // 9216
constexpr int NSTAGE  = 3;
constexpr int GSMEM   = NSTAGE * STAGE_F * 4;          // 110592
constexpr int QKSMEM  = GSMEM + 3 * 128 * 4;           // +cf/rf/rfl
constexpr int NTHR    = 512;
}

// ---------------- scratch ----------------
__device__ float g_xp[(size_t)ROWS * Ee];
__device__ float g_h [(size_t)ROWS * Ee];
__device__ float g_up[(size_t)ROWS * 2 * INNER];
__device__ float g_xc[(size_t)ROWS * INNER];
__device__ float g_q [(size_t)ROWS * INNER];
__device__ float g_k [(size_t)ROWS * INNER];
__device__ float g_v [(size_t)ROWS * INNER];
__device__ float g_vT[(size_t)BNH * DHd * Ss];
__device__ float g_ig[BNH * Ss];
__device__ float g_fg[BNH * Ss];
__device__ float g_e [BNH * Ss];
__device__ float g_pm[BNH * Ss];
__device__ float g_md[BNH * Ss];
__device__ float g_n [BNH * Ss];
__device__ float g_C [(size_t)BNH * Ss * Ss];
__device__ float g_hh[(size_t)BNH * Ss * DHd];
__device__ float g_hs[(size_t)ROWS * INNER];
__device__ float g_y [(size_t)ROWS * Ee];
__device__ float g_xr[(size_t)ROWS * FIN];
__device__ float g_Wi[(size_t)Ee * FIN];
__device__ float g_Wu[(size_t)2 * INNER * Ee];
__device__ float g_Wd[(size_t)Ee * INNER];

// ---------------- helpers ----------------
__device__ __forceinline__ float tf32r(float x) {
    uint32_t u;
    asm("cvt.rna.tf32.f32 %0, %1;" : "=r"(u) : "f"(x));
    return __uint_as_float(u);
}
__device__ __forceinline__ void mma_tf32(float* c, const uint32_t* a, const uint32_t* b) {
    asm volatile(
        "mma.sync.aligned.m16n8k8.row.col.f32.tf32.tf32.f32 "
        "{%0,%1,%2,%3}, {%4,%5,%6,%7}, {%8,%9}, {%0,%1,%2,%3};"
        : "+f"(c[0]), "+f"(c[1]), "+f"(c[2]), "+f"(c[3])
        : "r"(a[0]), "r"(a[1]), "r"(a[2]), "r"(a[3]), "r"(b[0]), "r"(b[1]));
}
__device__ __forceinline__ uint32_t smem_u32(const void* p) {
    uint32_t a;
    asm("{ .reg .u64 t; cvta.to.shared.u64 t, %1; cvt.u32.u64 %0, t; }" : "=r"(a) : "l"(p));
    return a;
}
#define CP16(dst, src) \
    asm volatile("cp.async.cg.shared.global [%0], [%1], 16;" :: "r"(dst), "l"(src) : "memory")
#define CP_COMMIT() asm volatile("cp.async.commit_group;" ::: "memory")
#define CP_WAIT(n)  asm volatile("cp.async.wait_group %0;" :: "n"(n) : "memory")

// single-pass dual block reduction: (a, b) summed simultaneously
__device__ __forceinline__ void blockReduceSum2(float& a, float& b) {
    __shared__ float sh[66];
    int lane = threadIdx.x & 31, wid = threadIdx.x >> 5;
    #pragma unroll
    for (int o = 16; o; o >>= 1) {
        a += __shfl_down_sync(0xffffffffu, a, o);
        b += __shfl_down_sync(0xffffffffu, b, o);
    }
    if (lane == 0) { sh[wid] = a; sh[33 + wid] = b; }
    __syncthreads();
    int nw = blockDim.x >> 5;
    float ta = (threadIdx.x < nw) ? sh[threadIdx.x] : 0.f;
    float tb = (threadIdx.x < nw) ? sh[33 + threadIdx.x] : 0.f;
    if (wid == 0) {
        #pragma unroll
        for (int o = 16; o; o >>= 1) {
            ta += __shfl_down_sync(0xffffffffu, ta, o);
            tb += __shfl_down_sync(0xffffffffu, tb, o);
        }
        if (lane == 0) { sh[32] = ta; sh[65] = tb; }
    }
    __syncthreads();
    a = sh[32];
    b = sh[65];
    __syncthreads();
}

// ---------------- GEMM machinery (512 threads, 4x4 warps, 32x32/warp) -------
__device__ __forceinline__ void g_load_tile(uint32_t sb, int stage,
                                            const float* A, const float* B,
                                            int kt, int lda, int ldb) {
    int lrow = threadIdx.x >> 2;          // 0..127
    int lch  = (threadIdx.x & 3) * 2;     // chunk pair {lch, lch+1} of 8
    uint32_t abase = sb + (uint32_t)(stage * STAGE_F) * 4 + lrow * (ROWSTR * 4);
    uint32_t bbase = abase + TILE_F * 4;
    const float* ap = A + (long)lrow * lda + kt * KT + lch * 4;
    const float* bp = B + (long)lrow * ldb + kt * KT + lch * 4;
    #pragma unroll
    for (int i = 0; i < 2; ++i) {
        CP16(abase + (lch + i) * 16, ap + i * 4);
        CP16(bbase + (lch + i) * 16, bp + i * 4);
    }
}

__device__ __forceinline__ void g_compute_tile(const float* As, const float* Bs,
                                               int wm, int wn, int gid, int tig,
                                               float acc[2][4][4]) {
    #pragma unroll
    for (int ks = 0; ks < 4; ++ks) {
        int kc = ks * 8;
        uint32_t a[2][4], b[4][2];
        #pragma unroll
        for (int mi = 0; mi < 2; ++mi) {
            int r = wm * 32 + mi * 16 + gid;
            a[mi][0] = __float_as_uint(As[r * ROWSTR + kc + tig]);
            a[mi][1] = __float_as_uint(As[(r + 8) * ROWSTR + kc + tig]);
            a[mi][2] = __float_as_uint(As[r * ROWSTR + kc + tig + 4]);
            a[mi][3] = __float_as_uint(As[(r + 8) * ROWSTR + kc + tig + 4]);
        }
        #pragma unroll
        for (int ni = 0; ni < 4; ++ni) {
            int n = wn * 32 + ni * 8 + gid;
            b[ni][0] = __float_as_uint(Bs[n * ROWSTR + kc + tig]);
            b[ni][1] = __float_as_uint(Bs[n * ROWSTR + kc + tig + 4]);
        }
        #pragma unroll
        for (int mi = 0; mi < 2; ++mi)
            #pragma unroll
            for (int ni = 0; ni < 4; ++ni)
                mma_tf32(acc[mi][ni], a[mi], b[ni]);
    }
}

// 3-stage mainloop (R7/R12-proven): one __syncthreads per K-tile; CP_WAIT(1)
#define GEMM_MAINLOOP(Aptr, Bptr, LDA, LDB)                                  \
    g_load_tile(sb, 0, Aptr, Bptr, 0, LDA, LDB);                             \
    CP_COMMIT();                                                             \
    if (nT > 1) { g_load_tile(sb, 1, Aptr, Bptr, 1, LDA, LDB); CP_COMMIT(); }\
    for (int kt = 0; kt < nT; ++kt) {                                        \
        if (kt + 1 < nT) { CP_WAIT(1); } else { CP_WAIT(0); }                \
        __syncthreads();                                                     \
        int nx = kt + 2;                                                     \
        if (nx < nT) { g_load_tile(sb, nx % 3, Aptr, Bptr, nx, LDA, LDB);    \
                       CP_COMMIT(); }                                        \
        g_compute_tile(sm + (kt % 3) * STAGE_F,                              \
                       sm + (kt % 3) * STAGE_F + TILE_F,                     \
                       wm, wn, gid, tig, acc);                               \
    }

// ---------------- general GEMM: C = A(M,K) * B(N,K)^T [+bias] --------------
template<int TRI>   // TRI=0 full, TRI=2 K limited to (by+1)*128
__global__ void __launch_bounds__(NTHR, 2)
mma_gemm(const float* __restrict__ Ag, const float* __restrict__ Bg,
         float* __restrict__ Cg, const float* __restrict__ bias,
         int K, int lda, int ldb, int ldc,
         long aOffB, long aOffN, long bOffB, long bOffN, long cOffB, long cOffN) {
    int bx = blockIdx.x, by = blockIdx.y, z = blockIdx.z;
    extern __shared__ float sm[];
    uint32_t sb = smem_u32(sm);
    const float* A = Ag + (long)(z >> 2) * aOffB + (long)(z & 3) * aOffN + (long)by * 128 * lda;
    const float* B = Bg + (long)(z >> 2) * bOffB + (long)(z & 3) * bOffN + (long)bx * 128 * ldb;
    float*       Cp = Cg + (long)(z >> 2) * cOffB + (long)(z & 3) * cOffN;

    int Keff = (TRI == 2) ? min(K, (by + 1) * 128) : K;
    int nT = Keff / KT;

    int tid = threadIdx.x, wid = tid >> 5, lane = tid & 31;
    int wm = wid >> 2, wn = wid & 3;
    int gid = lane >> 2, tig = lane & 3;

    float acc[2][4][4] = {};
    GEMM_MAINLOOP(A, B, lda, ldb)

    long m0 = (long)by * 128 + wm * 32;
    long n0 = (long)bx * 128 + wn * 32;
    #pragma unroll
    for (int mi = 0; mi < 2; ++mi) {
        #pragma unroll
        for (int ni = 0; ni < 4; ++ni) {
            long r = m0 + mi * 16 + gid;
            long c = n0 + ni * 8 + tig * 2;
            float b0 = bias ? bias[c] : 0.f, b1 = bias ? bias[c + 1] : 0.f;
            float2 v0 = {acc[mi][ni][0] + b0, acc[mi][ni][1] + b1};
            float2 v1 = {acc[mi][ni][2] + b0, acc[mi][ni][3] + b1};
            *(float2*)(Cp + r * ldc + c) = v0;
            *(float2*)(Cp + (r + 8) * ldc + c) = v1;
        }
    }
}

// ---------------- fused QK^T + decay + mask + rowsum -------------------------
// Dead causal blocks (bx>by) are repurposed to transpose v -> vT for this head.
__global__ void __launch_bounds__(NTHR, 2)
qk_fused(const float* __restrict__ qg, const float* __restrict__ kg,
         float* __restrict__ Cg, const float* __restrict__ eg,
         const float* __restrict__ pmg, float* __restrict__ nsum) {
    int bx = blockIdx.x, by = blockIdx.y, z = blockIdx.z;
    extern __shared__ float sm[];

    if (bx > by) {
        // ---- v transpose for head z: tiles strided over the 28 dead blocks
        int d = bx * (bx - 1) / 2 + by;     // 0..27
        int tx = threadIdx.x & 31, ty = threadIdx.x >> 5;   // 32 x 16
        int b = z >> 2, n = z & 3;
        float* tb = sm;                      // 32x33 staging
        for (int t = d; t < 256; t += 28) {
            int s0 = (t & 7) * 128 + ((t >> 3) & 3) * 32;   // unused split? keep simple:
            // map t -> (si, di): si = t % 32 (s-tile), di = t / 32 (d-tile)
            int si = t & 31, di = t >> 5;
            s0 = si * 32;
            int d0 = di * 32;
            #pragma unroll
            for (int r = 0; r < 32; r += 16)
                tb[(r + ty) * 33 + tx] =
                    g_v[((long)b * Ss + s0 + r + ty) * INNER + n * DHd + d0 + tx];
            __syncthreads();
            #pragma unroll
            for (int r = 0; r < 32; r += 16)
                g_vT[((long)z * DHd + d0 + r + ty) * Ss + s0 + tx] = tb[tx * 33 + r + ty];
            __syncthreads();
        }
        return;
    }

    uint32_t sb = smem_u32(sm);
    int tid = threadIdx.x, wid = tid >> 5, lane = tid & 31;
    int wm = wid >> 2, wn = wid & 3;
    int gid = lane >> 2, tig = lane & 3;

    const float* A = qg + (long)(z >> 2) * Ss * INNER + (long)(z & 3) * DHd + (long)by * 128 * INNER;
    const float* B = kg + (long)(z >> 2) * Ss * INNER + (long)(z & 3) * DHd + (long)bx * 128 * INNER;
    float* Cp = Cg + (long)z * Ss * Ss;
    const float* e_r  = eg  + (long)z * Ss;
    const float* pm_r = pmg + (long)z * Ss;
    int s0 = by * 128, t0 = bx * 128;
    float P = pm_r[s0 + 127];

    float* cf  = sm + NSTAGE * STAGE_F;
    float* rf  = cf + 128;
    float* rfl = rf + 128;
    if (tid < 128) {
        int j = tid;
        cf[j] = expf(e_r[t0 + j] - P) * 0.0625f;
        float rl = P - pm_r[s0 + j];
        rfl[j] = rl;
        rf[j] = expf(fminf(rl, 60.f));
    }

    float acc[2][4][4] = {};
    const int nT = DHd / KT;   // 8
    GEMM_MAINLOOP(A, B, INNER, INNER)

    bool diag = (bx == by);
    #pragma unroll
    for (int mi = 0; mi < 2; ++mi) {
        int r0 = wm * 32 + mi * 16 + gid;
        float rl0 = rfl[r0], rl1 = rfl[r0 + 8];
        bool  sl0 = rl0 > 60.f, sl1 = rl1 > 60.f;
        float rv0 = rf[r0], rv1 = rf[r0 + 8];
        float pm0 = P - rl0, pm1 = P - rl1;
        float sum0 = 0.f, sum1 = 0.f;
        #pragma unroll
        for (int ni = 0; ni < 4; ++ni) {
            int cidx = wn * 32 + ni * 8 + tig * 2;
            float c0 = cf[cidx], c1 = cf[cidx + 1];
            float v00, v01, v10, v11;
            if (!sl0) { v00 = acc[mi][ni][0] * c0 * rv0; v01 = acc[mi][ni][1] * c1 * rv0; }
            else {
                v00 = acc[mi][ni][0] * 0.0625f * expf(e_r[t0 + cidx]     - pm0);
                v01 = acc[mi][ni][1] * 0.0625f * expf(e_r[t0 + cidx + 1] - pm0);
            }
            if (!sl1) { v10 = acc[mi][ni][2] * c0 * rv1; v11 = acc[mi][ni][3] * c1 * rv1; }
            else {
                v10 = acc[mi][ni][2] * 0.0625f * expf(e_r[t0 + cidx]     - pm1);
                v11 = acc[mi][ni][3] * 0.0625f * expf(e_r[t0 + cidx + 1] - pm1);
            }
            if (diag) {
                if (cidx     > r0)     v00 = 0.f;
                if (cidx + 1 > r0)     v01 = 0.f;
                if (cidx     > r0 + 8) v10 = 0.f;
                if (cidx + 1 > r0 + 8) v11 = 0.f;
            }
            sum0 += v00 + v01;
            sum1 += v10 + v11;
            float2 w0 = {tf32r(v00), tf32r(v01)};
            float2 w1 = {tf32r(v10), tf32r(v11)};
            *(float2*)(Cp + (long)(s0 + r0)     * Ss + t0 + cidx) = w0;
            *(float2*)(Cp + (long)(s0 + r0 + 8) * Ss + t0 + cidx) = w1;
        }
        sum0 += __shfl_xor_sync(0xffffffffu, sum0, 1);
        sum0 += __shfl_xor_sync(0xffffffffu, sum0, 2);
        sum1 += __shfl_xor_sync(0xffffffffu, sum1, 1);
        sum1 += __shfl_xor_sync(0xffffffffu, sum1, 2);
        if (tig == 0) {
            atomicAdd(&nsum[(long)z * Ss + s0 + r0], sum0);
            atomicAdd(&nsum[(long)z * Ss + s0 + r0 + 8], sum1);
        }
    }
}

// ---------------- prep: tf32-round all operands + zero g_n ------------------
__global__ void prep_all(const float* __restrict__ x, const float* __restrict__ Wi,
                         const float* __restrict__ Wu, const float* __restrict__ Wd) {
    const int n1 = ROWS * FIN / 4, n2 = Ee * FIN / 4,
              n3 = 2 * INNER * Ee / 4, n4 = Ee * INNER / 4, n5 = BNH * Ss / 4;
    int i = blockIdx.x * 256 + threadIdx.x;
    const float4* src; float4* dst; int j = i;
    if (j < n1)            { src = (const float4*)x;  dst = (float4*)g_xr; }
    else if ((j -= n1) < n2) { src = (const float4*)Wi; dst = (float4*)g_Wi; }
    else if ((j -= n2) < n3) { src = (const float4*)Wu; dst = (float4*)g_Wu; }
    else if ((j -= n3) < n4) { src = (const float4*)Wd; dst = (float4*)g_Wd; }
    else if ((j -= n4) < n5) { ((float4*)g_n)[j] = make_float4(0, 0, 0, 0); return; }
    else return;
    float4 v = src[j];
    v.x = tf32r(v.x); v.y = tf32r(v.y); v.z = tf32r(v.z); v.w = tf32r(v.w);
    dst[j] = v;
}

// ---------------- row LayerNorm; RND=1 rounds output to tf32 ---------------
template<int RND>
__global__ void ln_rows(const float* __restrict__ in, const float* __restrict__ w,
                        float* __restrict__ out, int W) {
    long row = blockIdx.x;
    const float* p = in + row * (long)W;
    float s = 0.f, s2 = 0.f;
    for (int j = threadIdx.x; j < W; j += blockDim.x) { float v = p[j]; s += v; s2 += v * v; }
    blockReduceSum2(s, s2);
    float mu  = s / W;
    float var = s2 / W - mu * mu;
    float r = rsqrtf(var + 1e-5f);
    for (int j = threadIdx.x; j < W; j += blockDim.x) {
        float o = (p[j] - mu) * r * w[j];
        out[row * (long)W + j] = RND ? tf32r(o) : o;
    }
}

// ---------------- fused conv+SiLU+headwise (R7 version) ---------------------
__global__ void __launch_bounds__(256)
conv_head(const float* __restrict__ cw, const float* __restrict__ cb,
          const float* __restrict__ Wq, const float* __restrict__ Wk,
          const float* __restrict__ Wv) {
    __shared__ float xc_s[INNER];
    long row = blockIdx.x;
    int  t   = (int)(row & (Ss - 1));
    int tid = threadIdx.x;
    #pragma unroll
    for (int l = 0; l < 4; ++l) {
        int c = tid + l * 256;
        float acc = cb[c];
        #pragma unroll
        for (int j = 0; j < KSk; ++j) {
            int dt = j - (KSk - 1);
            if (t + dt >= 0)
                acc += g_up[(row + dt) * (2 * INNER) + c] * cw[c * KSk + j];
        }
        float s = acc / (1.f + expf(-acc));
        xc_s[c] = s;
        g_xc[row * INNER + c] = s;
    }
    __syncthreads();
    int nb = tid;
    long base = row * INNER + nb * 4;
    float4 xm = *(const float4*)&g_up[row * (2 * INNER) + nb * 4];
    float xc4[4] = {xc_s[nb * 4], xc_s[nb * 4 + 1], xc_s[nb * 4 + 2], xc_s[nb * 4 + 3]};
    float xm4[4] = {xm.x, xm.y, xm.z, xm.w};
    float qo[4], ko[4], vo[4];
    #pragma unroll
    for (int o = 0; o < 4; ++o) {
        float q = 0.f, k = 0.f, v = 0.f;
        #pragma unroll
        for (int i = 0; i < 4; ++i) {
            q += xc4[i] * Wq[nb * 16 + o * 4 + i];
            k += xc4[i] * Wk[nb * 16 + o * 4 + i];
            v += xm4[i] * Wv[nb * 16 + o * 4 + i];
        }
        qo[o] = tf32r(q); ko[o] = tf32r(k); vo[o] = tf32r(v);
    }
    *(float4*)&g_q[base] = *(float4*)qo;
    *(float4*)&g_k[base] = *(float4*)ko;
    *(float4*)&g_v[base] = *(float4*)vo;
}

// ---------------- gate projections (paired reductions) -----------------------
__global__ void gates(const float* __restrict__ Wig, const float* __restrict__ big,
                      const float* __restrict__ Wfg, const float* __restrict__ bfg) {
    long row = blockIdx.x;
    float aI[4] = {0, 0, 0, 0}, aF[4] = {0, 0, 0, 0};
    for (int c = threadIdx.x; c < INNER; c += blockDim.x) {
        float qv = g_q[row * INNER + c];
        float kv = g_k[row * INNER + c];
        float vv = g_v[row * INNER + c];
        #pragma unroll
        for (int n = 0; n < 4; ++n) {
            const float* wi = Wig + (long)n * 3 * INNER;
            const float* wf = Wfg + (long)n * 3 * INNER;
            aI[n] += qv * wi[c] + kv * wi[INNER + c] + vv * wi[2 * INNER + c];
            aF[n] += qv * wf[c] + kv * wf[INNER + c] + vv * wf[2 * INNER + c];
        }
    }
    int b = (int)(row >> 10), s = (int)(row & 1023);
    #pragma unroll
    for (int n = 0; n < 4; ++n) {
        blockReduceSum2(aI[n], aF[n]);
        if (threadIdx.x == 0) {
            g_ig[(b * NHh + n) * Ss + s] = aI[n] + big[n];
            g_fg[(b * NHh + n) * Ss + s] = aF[n] + bfg[n];
        }
    }
}

// ---------------- parallel gate scan (one block per bn, 1024 threads) -------
__global__ void __launch_bounds__(1024)
gate_scan_par() {
    __shared__ float wsum[32];
    int bn = blockIdx.x;
    int t = threadIdx.x, lane = t & 31, wid = t >> 5;
    float f  = g_fg[bn * Ss + t];
    float lf = fminf(f, 0.f) - log1pf(expf(-fabsf(f)));   // log_sigmoid

    float v = lf;
    #pragma unroll
    for (int o = 1; o < 32; o <<= 1) {
        float nv = __shfl_up_sync(0xffffffffu, v, o);
        if (lane >= o) v += nv;
    }
    if (lane == 31) wsum[wid] = v;
    __syncthreads();
    if (wid == 0) {
        float w = wsum[lane];
        #pragma unroll
        for (int o = 1; o < 32; o <<= 1) {
            float nv = __shfl_up_sync(0xffffffffu, w, o);
            if (lane >= o) w += nv;
        }
        wsum[lane] = w;
    }
    __syncthreads();
    float a = v + (wid > 0 ? wsum[wid - 1] : 0.f);

    float e = g_ig[bn * Ss + t] - a;
    __syncthreads();

    float m = e;
    #pragma unroll
    for (int o = 1; o < 32; o <<= 1) {
        float nv = __shfl_up_sync(0xffffffffu, m, o);
        if (lane >= o) m = fmaxf(m, nv);
    }
    if (lane == 31) wsum[wid] = m;
    __syncthreads();
    if (wid == 0) {
        float w = wsum[lane];
        #pragma unroll
        for (int o = 1; o < 32; o <<= 1) {
            float nv = __shfl_up_sync(0xffffffffu, w, o);
            if (lane >= o) w = fmaxf(w, nv);
        }
        wsum[lane] = w;
    }
    __syncthreads();
    float pm = (wid > 0) ? fmaxf(m, wsum[wid - 1]) : m;

    g_e [bn * Ss + t] = e;
    g_pm[bn * Ss + t] = pm;
    g_md[bn * Ss + t] = a + pm;
}

// ---------------- per-head LN + 1/n + skip + SiLU(z) gate -------------------
__global__ void mhln_combine(const float* __restrict__ mw, const float* __restrict__ skip) {
    int s  = blockIdx.x;
    int bn = blockIdx.y;
    int b = bn >> 2, n = bn & 3;
    int d = threadIdx.x;
    float rs = g_n[bn * Ss + s];
    float nn = fmaxf(fabsf(rs), expf(-g_md[bn * Ss + s]));
    float inv = 1.f / (nn + 1e-6f);
    size_t hrow = ((size_t)bn * Ss + s) * DHd;
    float x  = g_hh[hrow + d] * inv;
    float su = x, s2 = x * x;
    blockReduceSum2(su, s2);
    float mu  = su / DHd;
    float var = s2 / DHd - mu * mu;
    float hn = (x - mu) * rsqrtf(var + 1e-5f) * mw[n * DHd + d];
    int c = n * DHd + d;
    size_t row = (size_t)(b * Ss + s);
    float xc = g_xc[row * INNER + c];
    float z  = g_up[row * (2 * INNER) + INNER + c];
    float sz = z / (1.f + expf(-z));
    g_hs[row * INNER + c] = tf32r((hn + skip[c] * xc) * sz);
}

// ---------------- out = LN(res + y) -> d_out --------------------------------
__global__ void add_ln_out(const float* __restrict__ w, float* __restrict__ out) {
    long row = blockIdx.x;
    float vals[2];
    float s = 0.f, s2 = 0.f;
    #pragma unroll
    for (int l = 0; l < 2; ++l) {
        int j = threadIdx.x + l * 256;
        float v = g_xp[row * Ee + j] + g_y[row * Ee + j];
        vals[l] = v; s += v; s2 += v * v;
    }
    blockReduceSum2(s, s2);
    float mu  = s / Ee;
    float var = s2 / Ee - mu * mu;
    float r = rsqrtf(var + 1e-5f);
    #pragma unroll
    for (int l = 0; l < 2; ++l) {
        int j = threadIdx.x + l * 256;
        out[row * Ee + j] = (vals[l] - mu) * r * w[j];
    }
}

// ---------------- launch ----------------------------------------------------
extern "C" void kernel_launch(void* const* d_in, const int* /*in_sizes*/, int /*n_in*/,
                              void* d_out, int /*out_size*/) {
    const float* x         = (const float*)d_in[0];
    const float* W_in      = (const float*)d_in[1];
    const float* b_in      = (const float*)d_in[2];
    const float* ln1_w     = (const float*)d_in[3];
    const float* W_up      = (const float*)d_in[4];
    const float* conv_w    = (const float*)d_in[5];
    const float* conv_b    = (const float*)d_in[6];
    const float* Wq        = (const float*)d_in[7];
    const float* Wk        = (const float*)d_in[8];
    const float* Wv        = (const float*)d_in[9];
    const float* W_ig      = (const float*)d_in[10];
    const float* b_ig      = (const float*)d_in[11];
    const float* W_fg      = (const float*)d_in[12];
    const float* b_fg      = (const float*)d_in[13];
    const float* mhln_w    = (const float*)d_in[14];
    const float* skip      = (const float*)d_in[15];
    const float* W_down    = (const float*)d_in[16];
    const float* ln_post_w = (const float*)d_in[17];
    float* out = (float*)d_out;

    void *pxp, *ph, *pup, *pq, *pk, *pvT, *pC, *phh, *phs, *py;
    void *pxr, *pWi, *pWu, *pWd, *pe, *ppm, *pn;
    cudaGetSymbolAddress(&pxp, g_xp);
    cudaGetSymbolAddress(&ph,  g_h);
    cudaGetSymbolAddress(&pup, g_up);
    cudaGetSymbolAddress(&pq,  g_q);
    cudaGetSymbolAddress(&pk,  g_k);
    cudaGetSymbolAddress(&pvT, g_vT);
    cudaGetSymbolAddress(&pC,  g_C);
    cudaGetSymbolAddress(&phh, g_hh);
    cudaGetSymbolAddress(&phs, g_hs);
    cudaGetSymbolAddress(&py,  g_y);
    cudaGetSymbolAddress(&pxr, g_xr);
    cudaGetSymbolAddress(&pWi, g_Wi);
    cudaGetSymbolAddress(&pWu, g_Wu);
    cudaGetSymbolAddress(&pWd, g_Wd);
    cudaGetSymbolAddress(&pe,  g_e);
    cudaGetSymbolAddress(&ppm, g_pm);
    cudaGetSymbolAddress(&pn,  g_n);

    cudaFuncSetAttribute(mma_gemm<0>, cudaFuncAttributeMaxDynamicSharedMemorySize, GSMEM);
    cudaFuncSetAttribute(mma_gemm<2>, cudaFuncAttributeMaxDynamicSharedMemorySize, GSMEM);
    cudaFuncSetAttribute(qk_fused,    cudaFuncAttributeMaxDynamicSharedMemorySize, QKSMEM);

    // 0. prep: tf32-round operands, zero g_n
    {
        int total = ROWS * FIN / 4 + Ee * FIN / 4 + 2 * INNER * Ee / 4
                  + Ee * INNER / 4 + BNH * Ss / 4;
        prep_all<<<(total + 255) / 256, 256>>>(x, W_in, W_up, W_down);
    }

    // 1. xp = x @ W_in^T + b_in
    mma_gemm<0><<<dim3(Ee / 128, ROWS / 128, 1), NTHR, GSMEM>>>(
        (const float*)pxr, (const float*)pWi, (float*)pxp, b_in,
        FIN, FIN, FIN, Ee, 0, 0, 0, 0, 0, 0);

    // 2. h = LN(xp), tf32
    ln_rows<1><<<ROWS, 256>>>((const float*)pxp, ln1_w, (float*)ph, Ee);

    // 3. up = h @ W_up^T
    mma_gemm<0><<<dim3(2 * INNER / 128, ROWS / 128, 1), NTHR, GSMEM>>>(
        (const float*)ph, (const float*)pWu, (float*)pup, nullptr,
        Ee, Ee, Ee, 2 * INNER, 0, 0, 0, 0, 0, 0);

    // 4. fused conv+SiLU+headwise
    conv_head<<<ROWS, 256>>>(conv_w, conv_b, Wq, Wk, Wv);

    // 5. gates
    gates<<<ROWS, 256>>>(W_ig, b_ig, W_fg, b_fg);

    // 6. parallel gate scan
    gate_scan_par<<<BNH, 1024>>>();

    // 7. fused QK^T * decay + rowsum; dead causal blocks transpose v -> vT
    qk_fused<<<dim3(Ss / 128, Ss / 128, BNH), NTHR, QKSMEM>>>(
        (const float*)pq, (const float*)pk, (float*)pC,
        (const float*)pe, (const float*)ppm, (float*)pn);

    // 8. hh = C @ vT^T per head (K limited to causal extent)
    mma_gemm<2><<<dim3(DHd / 128, Ss / 128, BNH), NTHR, GSMEM>>>(
        (const float*)pC, (const float*)pvT, (float*)phh, nullptr,
        Ss, Ss, Ss, DHd,
        4L * Ss * Ss, (long)Ss * Ss,
        4L * DHd * Ss, (long)DHd * Ss,
        4L * Ss * DHd, (long)Ss * DHd);

    // 9. per-head LN + 1/n + combine
    mhln_combine<<<dim3(Ss, BNH), 256>>>(mhln_w, skip);

    // 10. y = h_state @ W_down^T
    mma_gemm<0><<<dim3(Ee / 128, ROWS / 128, 1), NTHR, GSMEM>>>(
        (const float*)phs, (const float*)pWd, (float*)py, nullptr,
        INNER, INNER, INNER, Ee, 0, 0, 0, 0, 0, 0);

    // 11. out = LN(res + y)
    add_ln_out<<<ROWS, 256>>>(ln_post_w, out);
}

// round 16
// speedup vs baseline: 2.0782x; 1.3460x over previous
#include <cuda_runtime.h>
#include <cuda_fp16.h>
#include <cstdint>
#include <math.h>

// ---------------- problem constants ----------------
namespace {
constexpr int Bb    = 8;
constexpr int Ss    = 1024;
constexpr int FIN   = 256;
constexpr int Ee    = 512;
constexpr int INNER = 1024;
constexpr int NHh   = 4;
constexpr int DHd   = 256;
constexpr int KSk   = 4;
constexpr int ROWS  = Bb * Ss;      // 8192
constexpr int BNH   = Bb * NHh;     // 32

// fp16 GEMM tile geometry (512 threads, 16 warps: 4x4 grid, 32x32 per warp)
constexpr int KT      = 64;                   // K halves per stage (128 B rows)
constexpr int STR32   = 36;                   // b32 per smem row (32 + 4 pad)
constexpr int TILE_B  = 128 * STR32 * 4;      // bytes per A or B tile (18432)
constexpr int STAGE_B = 2 * TILE_B;           // 36864
constexpr int NSTAGE  = 3;
constexpr int GSMEM   = NSTAGE * STAGE_B;     // 110592
constexpr int QKSMEM  = GSMEM + 3 * 128 * 4;  // +cf/rf/rfl
constexpr int NTHR    = 512;
}

// ---------------- scratch ----------------
__device__ float  g_xp[(size_t)ROWS * Ee];
__device__ __half g_h [(size_t)ROWS * Ee];
__device__ float  g_up[(size_t)ROWS * 2 * INNER];
__device__ float  g_xc[(size_t)ROWS * INNER];
__device__ __half g_q [(size_t)ROWS * INNER];
__device__ __half g_k [(size_t)ROWS * INNER];
__device__ __half g_v [(size_t)ROWS * INNER];
__device__ __half g_vT[(size_t)BNH * DHd * Ss];
__device__ float  g_ig[BNH * Ss];
__device__ float  g_fg[BNH * Ss];
__device__ float  g_e [BNH * Ss];
__device__ float  g_pm[BNH * Ss];
__device__ float  g_md[BNH * Ss];
__device__ float  g_n [BNH * Ss];
__device__ __half g_C [(size_t)BNH * Ss * Ss];   // 64 MB
__device__ float  g_hh[(size_t)BNH * Ss * DHd];
__device__ __half g_hs[(size_t)ROWS * INNER];
__device__ float  g_y [(size_t)ROWS * Ee];
__device__ __half g_xr[(size_t)ROWS * FIN];
__device__ __half g_Wi[(size_t)Ee * FIN];
__device__ __half g_Wu[(size_t)2 * INNER * Ee];
__device__ __half g_Wd[(size_t)Ee * INNER];

// ---------------- helpers ----------------
__device__ __forceinline__ void mma_f16(float* c, const uint32_t* a, const uint32_t* b) {
    asm volatile(
        "mma.sync.aligned.m16n8k16.row.col.f32.f16.f16.f32 "
        "{%0,%1,%2,%3}, {%4,%5,%6,%7}, {%8,%9}, {%0,%1,%2,%3};"
        : "+f"(c[0]), "+f"(c[1]), "+f"(c[2]), "+f"(c[3])
        : "r"(a[0]), "r"(a[1]), "r"(a[2]), "r"(a[3]), "r"(b[0]), "r"(b[1]));
}
__device__ __forceinline__ uint32_t smem_u32(const void* p) {
    uint32_t a;
    asm("{ .reg .u64 t; cvta.to.shared.u64 t, %1; cvt.u32.u64 %0, t; }" : "=r"(a) : "l"(p));
    return a;
}
#define CP16(dst, src) \
    asm volatile("cp.async.cg.shared.global [%0], [%1], 16;" :: "r"(dst), "l"(src) : "memory")
#define CP_COMMIT() asm volatile("cp.async.commit_group;" ::: "memory")
#define CP_WAIT(n)  asm volatile("cp.async.wait_group %0;" :: "n"(n) : "memory")

__device__ __forceinline__ void blockReduceSum2(float& a, float& b) {
    __shared__ float sh[66];
    int lane = threadIdx.x & 31, wid = threadIdx.x >> 5;
    #pragma unroll
    for (int o = 16; o; o >>= 1) {
        a += __shfl_down_sync(0xffffffffu, a, o);
        b += __shfl_down_sync(0xffffffffu, b, o);
    }
    if (lane == 0) { sh[wid] = a; sh[33 + wid] = b; }
    __syncthreads();
    int nw = blockDim.x >> 5;
    float ta = (threadIdx.x < nw) ? sh[threadIdx.x] : 0.f;
    float tb = (threadIdx.x < nw) ? sh[33 + threadIdx.x] : 0.f;
    if (wid == 0) {
        #pragma unroll
        for (int o = 16; o; o >>= 1) {
            ta += __shfl_down_sync(0xffffffffu, ta, o);
            tb += __shfl_down_sync(0xffffffffu, tb, o);
        }
        if (lane == 0) { sh[32] = ta; sh[65] = tb; }
    }
    __syncthreads();
    a = sh[32];
    b = sh[65];
    __syncthreads();
}

// ---------------- fp16 GEMM machinery (512 thr, 4x4 warps, 32x32/warp) ------
__device__ __forceinline__ void g_load_tile(uint32_t sb, int stage,
                                            const __half* A, const __half* B,
                                            int kt, int lda, int ldb) {
    int lrow = threadIdx.x >> 2;          // 0..127
    int lch  = (threadIdx.x & 3) * 2;     // chunk pair of 8 x 16B
    uint32_t abase = sb + (uint32_t)(stage * STAGE_B) + lrow * (STR32 * 4);
    uint32_t bbase = abase + TILE_B;
    const __half* ap = A + (long)lrow * lda + kt * KT + lch * 8;
    const __half* bp = B + (long)lrow * ldb + kt * KT + lch * 8;
    #pragma unroll
    for (int i = 0; i < 2; ++i) {
        CP16(abase + (lch + i) * 16, ap + i * 8);
        CP16(bbase + (lch + i) * 16, bp + i * 8);
    }
}

__device__ __forceinline__ void g_compute_tile(const uint32_t* As, const uint32_t* Bs,
                                               int wm, int wn, int gid, int tig,
                                               float acc[2][4][4]) {
    #pragma unroll
    for (int ks = 0; ks < 4; ++ks) {      // 4 x k16 = KT 64
        int kcb = ks * 8;                 // b32 offset (16 halves)
        uint32_t a[2][4], b[4][2];
        #pragma unroll
        for (int mi = 0; mi < 2; ++mi) {
            int r = wm * 32 + mi * 16 + gid;
            a[mi][0] = As[r * STR32 + kcb + tig];
            a[mi][1] = As[(r + 8) * STR32 + kcb + tig];
            a[mi][2] = As[r * STR32 + kcb + tig + 4];
            a[mi][3] = As[(r + 8) * STR32 + kcb + tig + 4];
        }
        #pragma unroll
        for (int ni = 0; ni < 4; ++ni) {
            int n = wn * 32 + ni * 8 + gid;
            b[ni][0] = Bs[n * STR32 + kcb + tig];
            b[ni][1] = Bs[n * STR32 + kcb + tig + 4];
        }
        #pragma unroll
        for (int mi = 0; mi < 2; ++mi)
            #pragma unroll
            for (int ni = 0; ni < 4; ++ni)
                mma_f16(acc[mi][ni], a[mi], b[ni]);
    }
}

#define GEMM_MAINLOOP(Aptr, Bptr, LDA, LDB)                                  \
    g_load_tile(sb, 0, Aptr, Bptr, 0, LDA, LDB);                             \
    CP_COMMIT();                                                             \
    if (nT > 1) { g_load_tile(sb, 1, Aptr, Bptr, 1, LDA, LDB); CP_COMMIT(); }\
    for (int kt = 0; kt < nT; ++kt) {                                        \
        if (kt + 1 < nT) { CP_WAIT(1); } else { CP_WAIT(0); }                \
        __syncthreads();                                                     \
        int nx = kt + 2;                                                     \
        if (nx < nT) { g_load_tile(sb, nx % 3, Aptr, Bptr, nx, LDA, LDB);    \
                       CP_COMMIT(); }                                        \
        g_compute_tile((const uint32_t*)(smc + (kt % 3) * STAGE_B),          \
                       (const uint32_t*)(smc + (kt % 3) * STAGE_B + TILE_B), \
                       wm, wn, gid, tig, acc);                               \
    }

// ---------------- general GEMM: C = A(M,K) * B(N,K)^T [+bias] --------------
template<int TRI>   // TRI=0 full, TRI=2 K limited to (by+1)*128
__global__ void __launch_bounds__(NTHR, 2)
mma_gemm(const __half* __restrict__ Ag, const __half* __restrict__ Bg,
         float* __restrict__ Cg, const float* __restrict__ bias,
         int K, int lda, int ldb, int ldc,
         long aOffB, long aOffN, long bOffB, long bOffN, long cOffB, long cOffN) {
    int bx = blockIdx.x, by = blockIdx.y, z = blockIdx.z;
    extern __shared__ char smc[];
    uint32_t sb = smem_u32(smc);
    const __half* A = Ag + (long)(z >> 2) * aOffB + (long)(z & 3) * aOffN + (long)by * 128 * lda;
    const __half* B = Bg + (long)(z >> 2) * bOffB + (long)(z & 3) * bOffN + (long)bx * 128 * ldb;
    float*        Cp = Cg + (long)(z >> 2) * cOffB + (long)(z & 3) * cOffN;

    int Keff = (TRI == 2) ? min(K, (by + 1) * 128) : K;
    int nT = Keff / KT;

    int tid = threadIdx.x, wid = tid >> 5, lane = tid & 31;
    int wm = wid >> 2, wn = wid & 3;
    int gid = lane >> 2, tig = lane & 3;

    float acc[2][4][4] = {};
    GEMM_MAINLOOP(A, B, lda, ldb)

    long m0 = (long)by * 128 + wm * 32;
    long n0 = (long)bx * 128 + wn * 32;
    #pragma unroll
    for (int mi = 0; mi < 2; ++mi) {
        #pragma unroll
        for (int ni = 0; ni < 4; ++ni) {
            long r = m0 + mi * 16 + gid;
            long c = n0 + ni * 8 + tig * 2;
            float b0 = bias ? bias[c] : 0.f, b1 = bias ? bias[c + 1] : 0.f;
            float2 v0 = {acc[mi][ni][0] + b0, acc[mi][ni][1] + b1};
            float2 v1 = {acc[mi][ni][2] + b0, acc[mi][ni][3] + b1};
            *(float2*)(Cp + r * ldc + c) = v0;
            *(float2*)(Cp + (r + 8) * ldc + c) = v1;
        }
    }
}

// ---------------- fused QK^T + decay + mask + rowsum (C stored fp16) --------
// Dead causal blocks (bx>by) transpose v -> vT for this head.
__global__ void __launch_bounds__(NTHR, 2)
qk_fused(const __half* __restrict__ qg, const __half* __restrict__ kg,
         __half* __restrict__ Cg, const float* __restrict__ eg,
         const float* __restrict__ pmg, float* __restrict__ nsum) {
    int bx = blockIdx.x, by = blockIdx.y, z = blockIdx.z;
    extern __shared__ char smc[];

    if (bx > by) {
        int d = bx * (bx - 1) / 2 + by;     // 0..27
        int tx = threadIdx.x & 31, ty = threadIdx.x >> 5;   // 32 x 16
        int b = z >> 2, n = z & 3;
        __half* tb = (__half*)smc;          // 32x33 staging
        for (int t = d; t < 256; t += 28) {
            int si = t & 31, di = t >> 5;
            int s0 = si * 32, d0 = di * 32;
            #pragma unroll
            for (int r = 0; r < 32; r += 16)
                tb[(r + ty) * 33 + tx] =
                    g_v[((long)b * Ss + s0 + r + ty) * INNER + n * DHd + d0 + tx];
            __syncthreads();
            #pragma unroll
            for (int r = 0; r < 32; r += 16)
                g_vT[((long)z * DHd + d0 + r + ty) * Ss + s0 + tx] = tb[tx * 33 + r + ty];
            __syncthreads();
        }
        return;
    }

    uint32_t sb = smem_u32(smc);
    int tid = threadIdx.x, wid = tid >> 5, lane = tid & 31;
    int wm = wid >> 2, wn = wid & 3;
    int gid = lane >> 2, tig = lane & 3;

    const __half* A = qg + (long)(z >> 2) * Ss * INNER + (long)(z & 3) * DHd + (long)by * 128 * INNER;
    const __half* B = kg + (long)(z >> 2) * Ss * INNER + (long)(z & 3) * DHd + (long)bx * 128 * INNER;
    __half* Cp = Cg + (long)z * Ss * Ss;
    const float* e_r  = eg  + (long)z * Ss;
    const float* pm_r = pmg + (long)z * Ss;
    int s0 = by * 128, t0 = bx * 128;
    float P = pm_r[s0 + 127];

    float* cf  = (float*)(smc + GSMEM);
    float* rf  = cf + 128;
    float* rfl = rf + 128;
    if (tid < 128) {
        int j = tid;
        cf[j] = expf(e_r[t0 + j] - P) * 0.0625f;
        float rl = P - pm_r[s0 + j];
        rfl[j] = rl;
        rf[j] = expf(fminf(rl, 60.f));
    }

    float acc[2][4][4] = {};
    const int nT = DHd / KT;   // 4
    GEMM_MAINLOOP(A, B, INNER, INNER)

    bool diag = (bx == by);
    #pragma unroll
    for (int mi = 0; mi < 2; ++mi) {
        int r0 = wm * 32 + mi * 16 + gid;
        float rl0 = rfl[r0], rl1 = rfl[r0 + 8];
        bool  sl0 = rl0 > 60.f, sl1 = rl1 > 60.f;
        float rv0 = rf[r0], rv1 = rf[r0 + 8];
        float pm0 = P - rl0, pm1 = P - rl1;
        float sum0 = 0.f, sum1 = 0.f;
        #pragma unroll
        for (int ni = 0; ni < 4; ++ni) {
            int cidx = wn * 32 + ni * 8 + tig * 2;
            float c0 = cf[cidx], c1 = cf[cidx + 1];
            float v00, v01, v10, v11;
            if (!sl0) { v00 = acc[mi][ni][0] * c0 * rv0; v01 = acc[mi][ni][1] * c1 * rv0; }
            else {
                v00 = acc[mi][ni][0] * 0.0625f * expf(e_r[t0 + cidx]     - pm0);
                v01 = acc[mi][ni][1] * 0.0625f * expf(e_r[t0 + cidx + 1] - pm0);
            }
            if (!sl1) { v10 = acc[mi][ni][2] * c0 * rv1; v11 = acc[mi][ni][3] * c1 * rv1; }
            else {
                v10 = acc[mi][ni][2] * 0.0625f * expf(e_r[t0 + cidx]     - pm1);
                v11 = acc[mi][ni][3] * 0.0625f * expf(e_r[t0 + cidx + 1] - pm1);
            }
            if (diag) {
                if (cidx     > r0)     v00 = 0.f;
                if (cidx + 1 > r0)     v01 = 0.f;
                if (cidx     > r0 + 8) v10 = 0.f;
                if (cidx + 1 > r0 + 8) v11 = 0.f;
            }
            sum0 += v00 + v01;
            sum1 += v10 + v11;
            *(__half2*)(Cp + (long)(s0 + r0)     * Ss + t0 + cidx) =
                __floats2half2_rn(v00, v01);
            *(__half2*)(Cp + (long)(s0 + r0 + 8) * Ss + t0 + cidx) =
                __floats2half2_rn(v10, v11);
        }
        sum0 += __shfl_xor_sync(0xffffffffu, sum0, 1);
        sum0 += __shfl_xor_sync(0xffffffffu, sum0, 2);
        sum1 += __shfl_xor_sync(0xffffffffu, sum1, 1);
        sum1 += __shfl_xor_sync(0xffffffffu, sum1, 2);
        if (tig == 0) {
            atomicAdd(&nsum[(long)z * Ss + s0 + r0], sum0);
            atomicAdd(&nsum[(long)z * Ss + s0 + r0 + 8], sum1);
        }
    }
}

// ---------------- prep: fp16-convert operands + zero g_n --------------------
__global__ void prep_all(const float* __restrict__ x, const float* __restrict__ Wi,
                         const float* __restrict__ Wu, const float* __restrict__ Wd) {
    const int n1 = ROWS * FIN / 4, n2 = Ee * FIN / 4,
              n3 = 2 * INNER * Ee / 4, n4 = Ee * INNER / 4, n5 = BNH * Ss / 4;
    int i = blockIdx.x * 256 + threadIdx.x;
    const float4* src; __half* dst; int j = i;
    if (j < n1)            { src = (const float4*)x;  dst = g_xr; }
    else if ((j -= n1) < n2) { src = (const float4*)Wi; dst = g_Wi; }
    else if ((j -= n2) < n3) { src = (const float4*)Wu; dst = g_Wu; }
    else if ((j -= n3) < n4) { src = (const float4*)Wd; dst = g_Wd; }
    else if ((j -= n4) < n5) { ((float4*)g_n)[j] = make_float4(0, 0, 0, 0); return; }
    else return;
    float4 v = src[j];
    __half2 lo = __floats2half2_rn(v.x, v.y);
    __half2 hi = __floats2half2_rn(v.z, v.w);
    *(uint2*)(dst + (long)j * 4) = make_uint2(*(uint32_t*)&lo, *(uint32_t*)&hi);
}

// ---------------- row LayerNorm -> fp16 out (for h) -------------------------
__global__ void ln_rows_h(const float* __restrict__ in, const float* __restrict__ w,
                          __half* __restrict__ out, int W) {
    long row = blockIdx.x;
    const float* p = in + row * (long)W;
    float s = 0.f, s2 = 0.f;
    for (int j = threadIdx.x; j < W; j += blockDim.x) { float v = p[j]; s += v; s2 += v * v; }
    blockReduceSum2(s, s2);
    float mu  = s / W;
    float var = s2 / W - mu * mu;
    float r = rsqrtf(var + 1e-5f);
    for (int j = threadIdx.x; j < W; j += blockDim.x)
        out[row * (long)W + j] = __float2half_rn((p[j] - mu) * r * w[j]);
}

// ---------------- fused conv+SiLU+headwise ----------------------------------
__global__ void __launch_bounds__(256)
conv_head(const float* __restrict__ cw, const float* __restrict__ cb,
          const float* __restrict__ Wq, const float* __restrict__ Wk,
          const float* __restrict__ Wv) {
    __shared__ float xc_s[INNER];
    long row = blockIdx.x;
    int  t   = (int)(row & (Ss - 1));
    int tid = threadIdx.x;
    #pragma unroll
    for (int l = 0; l < 4; ++l) {
        int c = tid + l * 256;
        float acc = cb[c];
        #pragma unroll
        for (int j = 0; j < KSk; ++j) {
            int dt = j - (KSk - 1);
            if (t + dt >= 0)
                acc += g_up[(row + dt) * (2 * INNER) + c] * cw[c * KSk + j];
        }
        float s = acc / (1.f + expf(-acc));
        xc_s[c] = s;
        g_xc[row * INNER + c] = s;
    }
    __syncthreads();
    int nb = tid;
    long base = row * INNER + nb * 4;
    float4 xm = *(const float4*)&g_up[row * (2 * INNER) + nb * 4];
    float xc4[4] = {xc_s[nb * 4], xc_s[nb * 4 + 1], xc_s[nb * 4 + 2], xc_s[nb * 4 + 3]};
    float xm4[4] = {xm.x, xm.y, xm.z, xm.w};
    float qo[4], ko[4], vo[4];
    #pragma unroll
    for (int o = 0; o < 4; ++o) {
        float q = 0.f, k = 0.f, v = 0.f;
        #pragma unroll
        for (int i = 0; i < 4; ++i) {
            q += xc4[i] * Wq[nb * 16 + o * 4 + i];
            k += xc4[i] * Wk[nb * 16 + o * 4 + i];
            v += xm4[i] * Wv[nb * 16 + o * 4 + i];
        }
        qo[o] = q; ko[o] = k; vo[o] = v;
    }
    __half2 q01 = __floats2half2_rn(qo[0], qo[1]), q23 = __floats2half2_rn(qo[2], qo[3]);
    __half2 k01 = __floats2half2_rn(ko[0], ko[1]), k23 = __floats2half2_rn(ko[2], ko[3]);
    __half2 v01 = __floats2half2_rn(vo[0], vo[1]), v23 = __floats2half2_rn(vo[2], vo[3]);
    *(uint2*)(g_q + base) = make_uint2(*(uint32_t*)&q01, *(uint32_t*)&q23);
    *(uint2*)(g_k + base) = make_uint2(*(uint32_t*)&k01, *(uint32_t*)&k23);
    *(uint2*)(g_v + base) = make_uint2(*(uint32_t*)&v01, *(uint32_t*)&v23);
}

// ---------------- gate projections (paired reductions) -----------------------
__global__ void gates(const float* __restrict__ Wig, const float* __restrict__ big,
                      const float* __restrict__ Wfg, const float* __restrict__ bfg) {
    long row = blockIdx.x;
    float aI[4] = {0, 0, 0, 0}, aF[4] = {0, 0, 0, 0};
    for (int c = threadIdx.x; c < INNER; c += blockDim.x) {
        float qv = __half2float(g_q[row * INNER + c]);
        float kv = __half2float(g_k[row * INNER + c]);
        float vv = __half2float(g_v[row * INNER + c]);
        #pragma unroll
        for (int n = 0; n < 4; ++n) {
            const float* wi = Wig + (long)n * 3 * INNER;
            const float* wf = Wfg + (long)n * 3 * INNER;
            aI[n] += qv * wi[c] + kv * wi[INNER + c] + vv * wi[2 * INNER + c];
            aF[n] += qv * wf[c] + kv * wf[INNER + c] + vv * wf[2 * INNER + c];
        }
    }
    int b = (int)(row >> 10), s = (int)(row & 1023);
    #pragma unroll
    for (int n = 0; n < 4; ++n) {
        blockReduceSum2(aI[n], aF[n]);
        if (threadIdx.x == 0) {
            g_ig[(b * NHh + n) * Ss + s] = aI[n] + big[n];
            g_fg[(b * NHh + n) * Ss + s] = aF[n] + bfg[n];
        }
    }
}

// ---------------- parallel gate scan ----------------------------------------
__global__ void __launch_bounds__(1024)
gate_scan_par() {
    __shared__ float wsum[32];
    int bn = blockIdx.x;
    int t = threadIdx.x, lane = t & 31, wid = t >> 5;
    float f  = g_fg[bn * Ss + t];
    float lf = fminf(f, 0.f) - log1pf(expf(-fabsf(f)));   // log_sigmoid

    float v = lf;
    #pragma unroll
    for (int o = 1; o < 32; o <<= 1) {
        float nv = __shfl_up_sync(0xffffffffu, v, o);
        if (lane >= o) v += nv;
    }
    if (lane == 31) wsum[wid] = v;
    __syncthreads();
    if (wid == 0) {
        float w = wsum[lane];
        #pragma unroll
        for (int o = 1; o < 32; o <<= 1) {
            float nv = __shfl_up_sync(0xffffffffu, w, o);
            if (lane >= o) w += nv;
        }
        wsum[lane] = w;
    }
    __syncthreads();
    float a = v + (wid > 0 ? wsum[wid - 1] : 0.f);

    float e = g_ig[bn * Ss + t] - a;
    __syncthreads();

    float m = e;
    #pragma unroll
    for (int o = 1; o < 32; o <<= 1) {
        float nv = __shfl_up_sync(0xffffffffu, m, o);
        if (lane >= o) m = fmaxf(m, nv);
    }
    if (lane == 31) wsum[wid] = m;
    __syncthreads();
    if (wid == 0) {
        float w = wsum[lane];
        #pragma unroll
        for (int o = 1; o < 32; o <<= 1) {
            float nv = __shfl_up_sync(0xffffffffu, w, o);
            if (lane >= o) w = fmaxf(w, nv);
        }
        wsum[lane] = w;
    }
    __syncthreads();
    float pm = (wid > 0) ? fmaxf(m, wsum[wid - 1]) : m;

    g_e [bn * Ss + t] = e;
    g_pm[bn * Ss + t] = pm;
    g_md[bn * Ss + t] = a + pm;
}

// ---------------- per-head LN + 1/n + skip + SiLU(z) gate -------------------
__global__ void mhln_combine(const float* __restrict__ mw, const float* __restrict__ skip) {
    int s  = blockIdx.x;
    int bn = blockIdx.y;
    int b = bn >> 2, n = bn & 3;
    int d = threadIdx.x;
    float rs = g_n[bn * Ss + s];
    float nn = fmaxf(fabsf(rs), expf(-g_md[bn * Ss + s]));
    float inv = 1.f / (nn + 1e-6f);
    size_t hrow = ((size_t)bn * Ss + s) * DHd;
    float x  = g_hh[hrow + d] * inv;
    float su = x, s2 = x * x;
    blockReduceSum2(su, s2);
    float mu  = su / DHd;
    float var = s2 / DHd - mu * mu;
    float hn = (x - mu) * rsqrtf(var + 1e-5f) * mw[n * DHd + d];
    int c = n * DHd + d;
    size_t row = (size_t)(b * Ss + s);
    float xc = g_xc[row * INNER + c];
    float z  = g_up[row * (2 * INNER) + INNER + c];
    float sz = z / (1.f + expf(-z));
    g_hs[row * INNER + c] = __float2half_rn((hn + skip[c] * xc) * sz);
}

// ---------------- out = LN(res + y) -> d_out --------------------------------
__global__ void add_ln_out(const float* __restrict__ w, float* __restrict__ out) {
    long row = blockIdx.x;
    float vals[2];
    float s = 0.f, s2 = 0.f;
    #pragma unroll
    for (int l = 0; l < 2; ++l) {
        int j = threadIdx.x + l * 256;
        float v = g_xp[row * Ee + j] + g_y[row * Ee + j];
        vals[l] = v; s += v; s2 += v * v;
    }
    blockReduceSum2(s, s2);
    float mu  = s / Ee;
    float var = s2 / Ee - mu * mu;
    float r = rsqrtf(var + 1e-5f);
    #pragma unroll
    for (int l = 0; l < 2; ++l) {
        int j = threadIdx.x + l * 256;
        out[row * Ee + j] = (vals[l] - mu) * r * w[j];
    }
}

// ---------------- launch ----------------------------------------------------
extern "C" void kernel_launch(void* const* d_in, const int* /*in_sizes*/, int /*n_in*/,
                              void* d_out, int /*out_size*/) {
    const float* x         = (const float*)d_in[0];
    const float* W_in      = (const float*)d_in[1];
    const float* b_in      = (const float*)d_in[2];
    const float* ln1_w     = (const float*)d_in[3];
    const float* W_up      = (const float*)d_in[4];
    const float* conv_w    = (const float*)d_in[5];
    const float* conv_b    = (const float*)d_in[6];
    const float* Wq        = (const float*)d_in[7];
    const float* Wk        = (const float*)d_in[8];
    const float* Wv        = (const float*)d_in[9];
    const float* W_ig      = (const float*)d_in[10];
    const float* b_ig      = (const float*)d_in[11];
    const float* W_fg      = (const float*)d_in[12];
    const float* b_fg      = (const float*)d_in[13];
    const float* mhln_w    = (const float*)d_in[14];
    const float* skip      = (const float*)d_in[15];
    const float* W_down    = (const float*)d_in[16];
    const float* ln_post_w = (const float*)d_in[17];
    float* out = (float*)d_out;

    void *pxp, *ph, *pup, *pq, *pk, *pvT, *pC, *phh, *phs, *py;
    void *pxr, *pWi, *pWu, *pWd, *pe, *ppm, *pn;
    cudaGetSymbolAddress(&pxp, g_xp);
    cudaGetSymbolAddress(&ph,  g_h);
    cudaGetSymbolAddress(&pup, g_up);
    cudaGetSymbolAddress(&pq,  g_q);
    cudaGetSymbolAddress(&pk,  g_k);
    cudaGetSymbolAddress(&pvT, g_vT);
    cudaGetSymbolAddress(&pC,  g_C);
    cudaGetSymbolAddress(&phh, g_hh);
    cudaGetSymbolAddress(&phs, g_hs);
    cudaGetSymbolAddress(&py,  g_y);
    cudaGetSymbolAddress(&pxr, g_xr);
    cudaGetSymbolAddress(&pWi, g_Wi);
    cudaGetSymbolAddress(&pWu, g_Wu);
    cudaGetSymbolAddress(&pWd, g_Wd);
    cudaGetSymbolAddress(&pe,  g_e);
    cudaGetSymbolAddress(&ppm, g_pm);
    cudaGetSymbolAddress(&pn,  g_n);

    cudaFuncSetAttribute(mma_gemm<0>, cudaFuncAttributeMaxDynamicSharedMemorySize, GSMEM);
    cudaFuncSetAttribute(mma_gemm<2>, cudaFuncAttributeMaxDynamicSharedMemorySize, GSMEM);
    cudaFuncSetAttribute(qk_fused,    cudaFuncAttributeMaxDynamicSharedMemorySize, QKSMEM);

    // 0. prep: fp16 operands, zero g_n
    {
        int total = ROWS * FIN / 4 + Ee * FIN / 4 + 2 * INNER * Ee / 4
                  + Ee * INNER / 4 + BNH * Ss / 4;
        prep_all<<<(total + 255) / 256, 256>>>(x, W_in, W_up, W_down);
    }

    // 1. xp = x @ W_in^T + b_in
    mma_gemm<0><<<dim3(Ee / 128, ROWS / 128, 1), NTHR, GSMEM>>>(
        (const __half*)pxr, (const __half*)pWi, (float*)pxp, b_in,
        FIN, FIN, FIN, Ee, 0, 0, 0, 0, 0, 0);

    // 2. h = LN(xp) -> fp16
    ln_rows_h<<<ROWS, 256>>>((const float*)pxp, ln1_w, (__half*)ph, Ee);

    // 3. up = h @ W_up^T  (FIX: pass device address of g_up, not the symbol)
    mma_gemm<0><<<dim3(2 * INNER / 128, ROWS / 128, 1), NTHR, GSMEM>>>(
        (const __half*)ph, (const __half*)pWu, (float*)pup, nullptr,
        Ee, Ee, Ee, 2 * INNER, 0, 0, 0, 0, 0, 0);

    // 4. fused conv+SiLU+headwise
    conv_head<<<ROWS, 256>>>(conv_w, conv_b, Wq, Wk, Wv);

    // 5. gates
    gates<<<ROWS, 256>>>(W_ig, b_ig, W_fg, b_fg);

    // 6. parallel gate scan
    gate_scan_par<<<BNH, 1024>>>();

    // 7. fused QK^T * decay + rowsum; dead causal blocks transpose v -> vT
    qk_fused<<<dim3(Ss / 128, Ss / 128, BNH), NTHR, QKSMEM>>>(
        (const __half*)pq, (const __half*)pk, (__half*)pC,
        (const float*)pe, (const float*)ppm, (float*)pn);

    // 8. hh = C @ vT^T per head (K limited to causal extent)
    mma_gemm<2><<<dim3(DHd / 128, Ss / 128, BNH), NTHR, GSMEM>>>(
        (const __half*)pC, (const __half*)pvT, (float*)phh, nullptr,
        Ss, Ss, Ss, DHd,
        4L * Ss * Ss, (long)Ss * Ss,
        4L * DHd * Ss, (long)DHd * Ss,
        4L * Ss * DHd, (long)Ss * DHd);

    // 9. per-head LN + 1/n + combine
    mhln_combine<<<dim3(Ss, BNH), 256>>>(mhln_w, skip);

    // 10. y = h_state @ W_down^T
    mma_gemm<0><<<dim3(Ee / 128, ROWS / 128, 1), NTHR, GSMEM>>>(
        (const __half*)phs, (const __half*)pWd, (float*)py, nullptr,
        INNER, INNER, INNER, Ee, 0, 0, 0, 0, 0, 0);

    // 11. out = LN(res + y)
    add_ln_out<<<ROWS, 256>>>(ln_post_w, out);
}

// round 17
// speedup vs baseline: 2.1846x; 1.0512x over previous
#include <cuda_runtime.h>
#include <cuda_fp16.h>
#include <cstdint>
#include <math.h>

// ---------------- problem constants ----------------
namespace {
constexpr int Bb    = 8;
constexpr int Ss    = 1024;
constexpr int FIN   = 256;
constexpr int Ee    = 512;
constexpr int INNER = 1024;
constexpr int NHh   = 4;
constexpr int DHd   = 256;
constexpr int KSk   = 4;
constexpr int ROWS  = Bb * Ss;      // 8192
constexpr int BNH   = Bb * NHh;     // 32

// fp16 GEMM tile geometry (512 threads, 16 warps: 4x4 grid, 32x32 per warp)
constexpr int KT      = 64;                   // K halves per stage (128 B rows)
constexpr int STR32   = 36;                   // b32 per smem row (32 + 4 pad)
constexpr int TILE_B  = 128 * STR32 * 4;      // bytes per A or B tile (18432)
constexpr int STAGE_B = 2 * TILE_B;           // 36864
constexpr int NSTAGE  = 3;
constexpr int GSMEM   = NSTAGE * STAGE_B;     // 110592
constexpr int QKSMEM  = GSMEM + 3 * 128 * 4;  // +cf/rf/rfl
constexpr int NTHR    = 512;
}

// ---------------- scratch ----------------
__device__ float  g_xp[(size_t)ROWS * Ee];
__device__ __half g_h [(size_t)ROWS * Ee];
__device__ float  g_up[(size_t)ROWS * 2 * INNER];
__device__ float  g_xc[(size_t)ROWS * INNER];
__device__ __half g_q [(size_t)ROWS * INNER];
__device__ __half g_k [(size_t)ROWS * INNER];
__device__ __half g_v [(size_t)ROWS * INNER];
__device__ __half g_vT[(size_t)BNH * DHd * Ss];
__device__ float  g_ig[BNH * Ss];
__device__ float  g_fg[BNH * Ss];
__device__ float  g_e [BNH * Ss];
__device__ float  g_pm[BNH * Ss];
__device__ float  g_md[BNH * Ss];
__device__ float  g_n [BNH * Ss];
__device__ __half g_C [(size_t)BNH * Ss * Ss];   // 64 MB
__device__ float  g_hh[(size_t)BNH * Ss * DHd];
__device__ __half g_hs[(size_t)ROWS * INNER];
__device__ float  g_y [(size_t)ROWS * Ee];
__device__ __half g_xr[(size_t)ROWS * FIN];
__device__ __half g_Wi[(size_t)Ee * FIN];
__device__ __half g_Wu[(size_t)2 * INNER * Ee];
__device__ __half g_Wd[(size_t)Ee * INNER];

// ---------------- helpers ----------------
__device__ __forceinline__ void mma_f16(float* c, const uint32_t* a, const uint32_t* b) {
    asm volatile(
        "mma.sync.aligned.m16n8k16.row.col.f32.f16.f16.f32 "
        "{%0,%1,%2,%3}, {%4,%5,%6,%7}, {%8,%9}, {%0,%1,%2,%3};"
        : "+f"(c[0]), "+f"(c[1]), "+f"(c[2]), "+f"(c[3])
        : "r"(a[0]), "r"(a[1]), "r"(a[2]), "r"(a[3]), "r"(b[0]), "r"(b[1]));
}
__device__ __forceinline__ uint32_t smem_u32(const void* p) {
    uint32_t a;
    asm("{ .reg .u64 t; cvta.to.shared.u64 t, %1; cvt.u32.u64 %0, t; }" : "=r"(a) : "l"(p));
    return a;
}
#define LDM4(r, addr) \
    asm volatile("ldmatrix.sync.aligned.m8n8.x4.shared.b16 {%0,%1,%2,%3}, [%4];" \
        : "=r"((r)[0]), "=r"((r)[1]), "=r"((r)[2]), "=r"((r)[3]) : "r"(addr))
#define CP16(dst, src) \
    asm volatile("cp.async.cg.shared.global [%0], [%1], 16;" :: "r"(dst), "l"(src) : "memory")
#define CP_COMMIT() asm volatile("cp.async.commit_group;" ::: "memory")
#define CP_WAIT(n)  asm volatile("cp.async.wait_group %0;" :: "n"(n) : "memory")

__device__ __forceinline__ void blockReduceSum2(float& a, float& b) {
    __shared__ float sh[66];
    int lane = threadIdx.x & 31, wid = threadIdx.x >> 5;
    #pragma unroll
    for (int o = 16; o; o >>= 1) {
        a += __shfl_down_sync(0xffffffffu, a, o);
        b += __shfl_down_sync(0xffffffffu, b, o);
    }
    if (lane == 0) { sh[wid] = a; sh[33 + wid] = b; }
    __syncthreads();
    int nw = blockDim.x >> 5;
    float ta = (threadIdx.x < nw) ? sh[threadIdx.x] : 0.f;
    float tb = (threadIdx.x < nw) ? sh[33 + threadIdx.x] : 0.f;
    if (wid == 0) {
        #pragma unroll
        for (int o = 16; o; o >>= 1) {
            ta += __shfl_down_sync(0xffffffffu, ta, o);
            tb += __shfl_down_sync(0xffffffffu, tb, o);
        }
        if (lane == 0) { sh[32] = ta; sh[65] = tb; }
    }
    __syncthreads();
    a = sh[32];
    b = sh[65];
    __syncthreads();
}

// ---------------- fp16 GEMM machinery (512 thr, 4x4 warps, 32x32/warp) ------
__device__ __forceinline__ void g_load_tile(uint32_t sb, int stage,
                                            const __half* A, const __half* B,
                                            int kt, int lda, int ldb) {
    int lrow = threadIdx.x >> 2;          // 0..127
    int lch  = (threadIdx.x & 3) * 2;     // chunk pair of 8 x 16B
    uint32_t abase = sb + (uint32_t)(stage * STAGE_B) + lrow * (STR32 * 4);
    uint32_t bbase = abase + TILE_B;
    const __half* ap = A + (long)lrow * lda + kt * KT + lch * 8;
    const __half* bp = B + (long)lrow * ldb + kt * KT + lch * 8;
    #pragma unroll
    for (int i = 0; i < 2; ++i) {
        CP16(abase + (lch + i) * 16, ap + i * 8);
        CP16(bbase + (lch + i) * 16, bp + i * 8);
    }
}

// fragment loads via ldmatrix.x4 (4 per k16-step instead of 16 LDS.32)
__device__ __forceinline__ void g_compute_tile(uint32_t aBase, uint32_t bBase,
                                               int wm, int wn, int lane,
                                               float acc[2][4][4]) {
    int q = lane >> 3, rid = lane & 7;
    uint32_t aA0 = aBase + (uint32_t)(((wm * 32 + (q & 1) * 8 + rid) * STR32 + (q >> 1) * 4) << 2);
    uint32_t aA1 = aA0 + (uint32_t)((16 * STR32) << 2);
    uint32_t bA0 = bBase + (uint32_t)(((wn * 32 + (q >> 1) * 8 + rid) * STR32 + (q & 1) * 4) << 2);
    uint32_t bA1 = bA0 + (uint32_t)((16 * STR32) << 2);
    #pragma unroll
    for (int ks = 0; ks < 4; ++ks) {
        uint32_t ko = ks * 32;            // 8 b32 = 32 bytes per k16 step
        uint32_t a0[4], a1[4], b0[4], b1[4];
        LDM4(a0, aA0 + ko);
        LDM4(a1, aA1 + ko);
        LDM4(b0, bA0 + ko);
        LDM4(b1, bA1 + ko);
        mma_f16(acc[0][0], a0, b0);
        mma_f16(acc[0][1], a0, b0 + 2);
        mma_f16(acc[0][2], a0, b1);
        mma_f16(acc[0][3], a0, b1 + 2);
        mma_f16(acc[1][0], a1, b0);
        mma_f16(acc[1][1], a1, b0 + 2);
        mma_f16(acc[1][2], a1, b1);
        mma_f16(acc[1][3], a1, b1 + 2);
    }
}

#define GEMM_MAINLOOP(Aptr, Bptr, LDA, LDB)                                  \
    g_load_tile(sb, 0, Aptr, Bptr, 0, LDA, LDB);                             \
    CP_COMMIT();                                                             \
    if (nT > 1) { g_load_tile(sb, 1, Aptr, Bptr, 1, LDA, LDB); CP_COMMIT(); }\
    for (int kt = 0; kt < nT; ++kt) {                                        \
        if (kt + 1 < nT) { CP_WAIT(1); } else { CP_WAIT(0); }                \
        __syncthreads();                                                     \
        int nx = kt + 2;                                                     \
        if (nx < nT) { g_load_tile(sb, nx % 3, Aptr, Bptr, nx, LDA, LDB);    \
                       CP_COMMIT(); }                                        \
        g_compute_tile(sb + (uint32_t)((kt % 3) * STAGE_B),                  \
                       sb + (uint32_t)((kt % 3) * STAGE_B + TILE_B),         \
                       wm, wn, lane, acc);                                   \
    }

// ---------------- general GEMM: C = A(M,K) * B(N,K)^T [+bias] --------------
template<int TRI>   // TRI=0 full, TRI=2 K limited to (by+1)*128
__global__ void __launch_bounds__(NTHR, 2)
mma_gemm(const __half* __restrict__ Ag, const __half* __restrict__ Bg,
         float* __restrict__ Cg, const float* __restrict__ bias,
         int K, int lda, int ldb, int ldc,
         long aOffB, long aOffN, long bOffB, long bOffN, long cOffB, long cOffN) {
    int bx = blockIdx.x, by = blockIdx.y, z = blockIdx.z;
    extern __shared__ char smc[];
    uint32_t sb = smem_u32(smc);
    const __half* A = Ag + (long)(z >> 2) * aOffB + (long)(z & 3) * aOffN + (long)by * 128 * lda;
    const __half* B = Bg + (long)(z >> 2) * bOffB + (long)(z & 3) * bOffN + (long)bx * 128 * ldb;
    float*        Cp = Cg + (long)(z >> 2) * cOffB + (long)(z & 3) * cOffN;

    int Keff = (TRI == 2) ? min(K, (by + 1) * 128) : K;
    int nT = Keff / KT;

    int tid = threadIdx.x, wid = tid >> 5, lane = tid & 31;
    int wm = wid >> 2, wn = wid & 3;
    int gid = lane >> 2, tig = lane & 3;

    float acc[2][4][4] = {};
    GEMM_MAINLOOP(A, B, lda, ldb)

    long m0 = (long)by * 128 + wm * 32;
    long n0 = (long)bx * 128 + wn * 32;
    #pragma unroll
    for (int mi = 0; mi < 2; ++mi) {
        #pragma unroll
        for (int ni = 0; ni < 4; ++ni) {
            long r = m0 + mi * 16 + gid;
            long c = n0 + ni * 8 + tig * 2;
            float b0 = bias ? bias[c] : 0.f, b1 = bias ? bias[c + 1] : 0.f;
            float2 v0 = {acc[mi][ni][0] + b0, acc[mi][ni][1] + b1};
            float2 v1 = {acc[mi][ni][2] + b0, acc[mi][ni][3] + b1};
            *(float2*)(Cp + r * ldc + c) = v0;
            *(float2*)(Cp + (r + 8) * ldc + c) = v1;
        }
    }
}

// ---------------- fused QK^T + decay + mask + rowsum (C stored fp16) --------
// Dead causal blocks (bx>by) transpose v -> vT for this head.
__global__ void __launch_bounds__(NTHR, 2)
qk_fused(const __half* __restrict__ qg, const __half* __restrict__ kg,
         __half* __restrict__ Cg, const float* __restrict__ eg,
         const float* __restrict__ pmg, float* __restrict__ nsum) {
    int bx = blockIdx.x, by = blockIdx.y, z = blockIdx.z;
    extern __shared__ char smc[];

    if (bx > by) {
        int d = bx * (bx - 1) / 2 + by;     // 0..27
        int tx = threadIdx.x & 31, ty = threadIdx.x >> 5;   // 32 x 16
        int b = z >> 2, n = z & 3;
        __half* tb = (__half*)smc;          // 32x33 staging
        for (int t = d; t < 256; t += 28) {
            int si = t & 31, di = t >> 5;
            int s0 = si * 32, d0 = di * 32;
            #pragma unroll
            for (int r = 0; r < 32; r += 16)
                tb[(r + ty) * 33 + tx] =
                    g_v[((long)b * Ss + s0 + r + ty) * INNER + n * DHd + d0 + tx];
            __syncthreads();
            #pragma unroll
            for (int r = 0; r < 32; r += 16)
                g_vT[((long)z * DHd + d0 + r + ty) * Ss + s0 + tx] = tb[tx * 33 + r + ty];
            __syncthreads();
        }
        return;
    }

    uint32_t sb = smem_u32(smc);
    int tid = threadIdx.x, wid = tid >> 5, lane = tid & 31;
    int wm = wid >> 2, wn = wid & 3;
    int gid = lane >> 2, tig = lane & 3;

    const __half* A = qg + (long)(z >> 2) * Ss * INNER + (long)(z & 3) * DHd + (long)by * 128 * INNER;
    const __half* B = kg + (long)(z >> 2) * Ss * INNER + (long)(z & 3) * DHd + (long)bx * 128 * INNER;
    __half* Cp = Cg + (long)z * Ss * Ss;
    const float* e_r  = eg  + (long)z * Ss;
    const float* pm_r = pmg + (long)z * Ss;
    int s0 = by * 128, t0 = bx * 128;
    float P = pm_r[s0 + 127];

    float* cf  = (float*)(smc + GSMEM);
    float* rf  = cf + 128;
    float* rfl = rf + 128;
    if (tid < 128) {
        int j = tid;
        cf[j] = expf(e_r[t0 + j] - P) * 0.0625f;
        float rl = P - pm_r[s0 + j];
        rfl[j] = rl;
        rf[j] = expf(fminf(rl, 60.f));
    }

    float acc[2][4][4] = {};
    const int nT = DHd / KT;   // 4
    GEMM_MAINLOOP(A, B, INNER, INNER)

    bool diag = (bx == by);
    #pragma unroll
    for (int mi = 0; mi < 2; ++mi) {
        int r0 = wm * 32 + mi * 16 + gid;
        float rl0 = rfl[r0], rl1 = rfl[r0 + 8];
        bool  sl0 = rl0 > 60.f, sl1 = rl1 > 60.f;
        float rv0 = rf[r0], rv1 = rf[r0 + 8];
        float pm0 = P - rl0, pm1 = P - rl1;
        float sum0 = 0.f, sum1 = 0.f;
        #pragma unroll
        for (int ni = 0; ni < 4; ++ni) {
            int cidx = wn * 32 + ni * 8 + tig * 2;
            float c0 = cf[cidx], c1 = cf[cidx + 1];
            float v00, v01, v10, v11;
            if (!sl0) { v00 = acc[mi][ni][0] * c0 * rv0; v01 = acc[mi][ni][1] * c1 * rv0; }
            else {
                v00 = acc[mi][ni][0] * 0.0625f * expf(e_r[t0 + cidx]     - pm0);
                v01 = acc[mi][ni][1] * 0.0625f * expf(e_r[t0 + cidx + 1] - pm0);
            }
            if (!sl1) { v10 = acc[mi][ni][2] * c0 * rv1; v11 = acc[mi][ni][3] * c1 * rv1; }
            else {
                v10 = acc[mi][ni][2] * 0.0625f * expf(e_r[t0 + cidx]     - pm1);
                v11 = acc[mi][ni][3] * 0.0625f * expf(e_r[t0 + cidx + 1] - pm1);
            }
            if (diag) {
                if (cidx     > r0)     v00 = 0.f;
                if (cidx + 1 > r0)     v01 = 0.f;
                if (cidx     > r0 + 8) v10 = 0.f;
                if (cidx + 1 > r0 + 8) v11 = 0.f;
            }
            sum0 += v00 + v01;
            sum1 += v10 + v11;
            *(__half2*)(Cp + (long)(s0 + r0)     * Ss + t0 + cidx) =
                __floats2half2_rn(v00, v01);
            *(__half2*)(Cp + (long)(s0 + r0 + 8) * Ss + t0 + cidx) =
                __floats2half2_rn(v10, v11);
        }
        sum0 += __shfl_xor_sync(0xffffffffu, sum0, 1);
        sum0 += __shfl_xor_sync(0xffffffffu, sum0, 2);
        sum1 += __shfl_xor_sync(0xffffffffu, sum1, 1);
        sum1 += __shfl_xor_sync(0xffffffffu, sum1, 2);
        if (tig == 0) {
            atomicAdd(&nsum[(long)z * Ss + s0 + r0], sum0);
            atomicAdd(&nsum[(long)z * Ss + s0 + r0 + 8], sum1);
        }
    }
}

// ---------------- prep: fp16-convert operands + zero g_n --------------------
__global__ void prep_all(const float* __restrict__ x, const float* __restrict__ Wi,
                         const float* __restrict__ Wu, const float* __restrict__ Wd) {
    const int n1 = ROWS * FIN / 4, n2 = Ee * FIN / 4,
              n3 = 2 * INNER * Ee / 4, n4 = Ee * INNER / 4, n5 = BNH * Ss / 4;
    int i = blockIdx.x * 256 + threadIdx.x;
    const float4* src; __half* dst; int j = i;
    if (j < n1)            { src = (const float4*)x;  dst = g_xr; }
    else if ((j -= n1) < n2) { src = (const float4*)Wi; dst = g_Wi; }
    else if ((j -= n2) < n3) { src = (const float4*)Wu; dst = g_Wu; }
    else if ((j -= n3) < n4) { src = (const float4*)Wd; dst = g_Wd; }
    else if ((j -= n4) < n5) { ((float4*)g_n)[j] = make_float4(0, 0, 0, 0); return; }
    else return;
    float4 v = src[j];
    __half2 lo = __floats2half2_rn(v.x, v.y);
    __half2 hi = __floats2half2_rn(v.z, v.w);
    *(uint2*)(dst + (long)j * 4) = make_uint2(*(uint32_t*)&lo, *(uint32_t*)&hi);
}

// ---------------- row LayerNorm -> fp16 out (for h) -------------------------
__global__ void ln_rows_h(const float* __restrict__ in, const float* __restrict__ w,
                          __half* __restrict__ out, int W) {
    long row = blockIdx.x;
    const float* p = in + row * (long)W;
    float s = 0.f, s2 = 0.f;
    for (int j = threadIdx.x; j < W; j += blockDim.x) { float v = p[j]; s += v; s2 += v * v; }
    blockReduceSum2(s, s2);
    float mu  = s / W;
    float var = s2 / W - mu * mu;
    float r = rsqrtf(var + 1e-5f);
    for (int j = threadIdx.x; j < W; j += blockDim.x)
        out[row * (long)W + j] = __float2half_rn((p[j] - mu) * r * w[j]);
}

// ---------------- fused conv+SiLU+headwise ----------------------------------
__global__ void __launch_bounds__(256)
conv_head(const float* __restrict__ cw, const float* __restrict__ cb,
          const float* __restrict__ Wq, const float* __restrict__ Wk,
          const float* __restrict__ Wv) {
    __shared__ float xc_s[INNER];
    long row = blockIdx.x;
    int  t   = (int)(row & (Ss - 1));
    int tid = threadIdx.x;
    #pragma unroll
    for (int l = 0; l < 4; ++l) {
        int c = tid + l * 256;
        float acc = cb[c];
        #pragma unroll
        for (int j = 0; j < KSk; ++j) {
            int dt = j - (KSk - 1);
            if (t + dt >= 0)
                acc += g_up[(row + dt) * (2 * INNER) + c] * cw[c * KSk + j];
        }
        float s = acc / (1.f + expf(-acc));
        xc_s[c] = s;
        g_xc[row * INNER + c] = s;
    }
    __syncthreads();
    int nb = tid;
    long base = row * INNER + nb * 4;
    float4 xm = *(const float4*)&g_up[row * (2 * INNER) + nb * 4];
    float xc4[4] = {xc_s[nb * 4], xc_s[nb * 4 + 1], xc_s[nb * 4 + 2], xc_s[nb * 4 + 3]};
    float xm4[4] = {xm.x, xm.y, xm.z, xm.w};
    float qo[4], ko[4], vo[4];
    #pragma unroll
    for (int o = 0; o < 4; ++o) {
        float q = 0.f, k = 0.f, v = 0.f;
        #pragma unroll
        for (int i = 0; i < 4; ++i) {
            q += xc4[i] * Wq[nb * 16 + o * 4 + i];
            k += xc4[i] * Wk[nb * 16 + o * 4 + i];
            v += xm4[i] * Wv[nb * 16 + o * 4 + i];
        }
        qo[o] = q; ko[o] = k; vo[o] = v;
    }
    __half2 q01 = __floats2half2_rn(qo[0], qo[1]), q23 = __floats2half2_rn(qo[2], qo[3]);
    __half2 k01 = __floats2half2_rn(ko[0], ko[1]), k23 = __floats2half2_rn(ko[2], ko[3]);
    __half2 v01 = __floats2half2_rn(vo[0], vo[1]), v23 = __floats2half2_rn(vo[2], vo[3]);
    *(uint2*)(g_q + base) = make_uint2(*(uint32_t*)&q01, *(uint32_t*)&q23);
    *(uint2*)(g_k + base) = make_uint2(*(uint32_t*)&k01, *(uint32_t*)&k23);
    *(uint2*)(g_v + base) = make_uint2(*(uint32_t*)&v01, *(uint32_t*)&v23);
}

// ---------------- gate projections (paired reductions) -----------------------
__global__ void gates(const float* __restrict__ Wig, const float* __restrict__ big,
                      const float* __restrict__ Wfg, const float* __restrict__ bfg) {
    long row = blockIdx.x;
    float aI[4] = {0, 0, 0, 0}, aF[4] = {0, 0, 0, 0};
    for (int c = threadIdx.x; c < INNER; c += blockDim.x) {
        float qv = __half2float(g_q[row * INNER + c]);
        float kv = __half2float(g_k[row * INNER + c]);
        float vv = __half2float(g_v[row * INNER + c]);
        #pragma unroll
        for (int n = 0; n < 4; ++n) {
            const float* wi = Wig + (long)n * 3 * INNER;
            const float* wf = Wfg + (long)n * 3 * INNER;
            aI[n] += qv * wi[c] + kv * wi[INNER + c] + vv * wi[2 * INNER + c];
            aF[n] += qv * wf[c] + kv * wf[INNER + c] + vv * wf[2 * INNER + c];
        }
    }
    int b = (int)(row >> 10), s = (int)(row & 1023);
    #pragma unroll
    for (int n = 0; n < 4; ++n) {
        blockReduceSum2(aI[n], aF[n]);
        if (threadIdx.x == 0) {
            g_ig[(b * NHh + n) * Ss + s] = aI[n] + big[n];
            g_fg[(b * NHh + n) * Ss + s] = aF[n] + bfg[n];
        }
    }
}

// ---------------- parallel gate scan ----------------------------------------
__global__ void __launch_bounds__(1024)
gate_scan_par() {
    __shared__ float wsum[32];
    int bn = blockIdx.x;
    int t = threadIdx.x, lane = t & 31, wid = t >> 5;
    float f  = g_fg[bn * Ss + t];
    float lf = fminf(f, 0.f) - log1pf(expf(-fabsf(f)));   // log_sigmoid

    float v = lf;
    #pragma unroll
    for (int o = 1; o < 32; o <<= 1) {
        float nv = __shfl_up_sync(0xffffffffu, v, o);
        if (lane >= o) v += nv;
    }
    if (lane == 31) wsum[wid] = v;
    __syncthreads();
    if (wid == 0) {
        float w = wsum[lane];
        #pragma unroll
        for (int o = 1; o < 32; o <<= 1) {
            float nv = __shfl_up_sync(0xffffffffu, w, o);
            if (lane >= o) w += nv;
        }
        wsum[lane] = w;
    }
    __syncthreads();
    float a = v + (wid > 0 ? wsum[wid - 1] : 0.f);

    float e = g_ig[bn * Ss + t] - a;
    __syncthreads();

    float m = e;
    #pragma unroll
    for (int o = 1; o < 32; o <<= 1) {
        float nv = __shfl_up_sync(0xffffffffu, m, o);
        if (lane >= o) m = fmaxf(m, nv);
    }
    if (lane == 31) wsum[wid] = m;
    __syncthreads();
    if (wid == 0) {
        float w = wsum[lane];
        #pragma unroll
        for (int o = 1; o < 32; o <<= 1) {
            float nv = __shfl_up_sync(0xffffffffu, w, o);
            if (lane >= o) w = fmaxf(w, nv);
        }
        wsum[lane] = w;
    }
    __syncthreads();
    float pm = (wid > 0) ? fmaxf(m, wsum[wid - 1]) : m;

    g_e [bn * Ss + t] = e;
    g_pm[bn * Ss + t] = pm;
    g_md[bn * Ss + t] = a + pm;
}

// ---------------- per-head LN + 1/n + skip + SiLU(z) gate -------------------
__global__ void mhln_combine(const float* __restrict__ mw, const float* __restrict__ skip) {
    int s  = blockIdx.x;
    int bn = blockIdx.y;
    int b = bn >> 2, n = bn & 3;
    int d = threadIdx.x;
    float rs = g_n[bn * Ss + s];
    float nn = fmaxf(fabsf(rs), expf(-g_md[bn * Ss + s]));
    float inv = 1.f / (nn + 1e-6f);
    size_t hrow = ((size_t)bn * Ss + s) * DHd;
    float x  = g_hh[hrow + d] * inv;
    float su = x, s2 = x * x;
    blockReduceSum2(su, s2);
    float mu  = su / DHd;
    float var = s2 / DHd - mu * mu;
    float hn = (x - mu) * rsqrtf(var + 1e-5f) * mw[n * DHd + d];
    int c = n * DHd + d;
    size_t row = (size_t)(b * Ss + s);
    float xc = g_xc[row * INNER + c];
    float z  = g_up[row * (2 * INNER) + INNER + c];
    float sz = z / (1.f + expf(-z));
    g_hs[row * INNER + c] = __float2half_rn((hn + skip[c] * xc) * sz);
}

// ---------------- out = LN(res + y) -> d_out --------------------------------
__global__ void add_ln_out(const float* __restrict__ w, float* __restrict__ out) {
    long row = blockIdx.x;
    float vals[2];
    float s = 0.f, s2 = 0.f;
    #pragma unroll
    for (int l = 0; l < 2; ++l) {
        int j = threadIdx.x + l * 256;
        float v = g_xp[row * Ee + j] + g_y[row * Ee + j];
        vals[l] = v; s += v; s2 += v * v;
    }
    blockReduceSum2(s, s2);
    float mu  = s / Ee;
    float var = s2 / Ee - mu * mu;
    float r = rsqrtf(var + 1e-5f);
    #pragma unroll
    for (int l = 0; l < 2; ++l) {
        int j = threadIdx.x + l * 256;
        out[row * Ee + j] = (vals[l] - mu) * r * w[j];
    }
}

// ---------------- launch ----------------------------------------------------
extern "C" void kernel_launch(void* const* d_in, const int* /*in_sizes*/, int /*n_in*/,
                              void* d_out, int /*out_size*/) {
    const float* x         = (const float*)d_in[0];
    const float* W_in      = (const float*)d_in[1];
    const float* b_in      = (const float*)d_in[2];
    const float* ln1_w     = (const float*)d_in[3];
    const float* W_up      = (const float*)d_in[4];
    const float* conv_w    = (const float*)d_in[5];
    const float* conv_b    = (const float*)d_in[6];
    const float* Wq        = (const float*)d_in[7];
    const float* Wk        = (const float*)d_in[8];
    const float* Wv        = (const float*)d_in[9];
    const float* W_ig      = (const float*)d_in[10];
    const float* b_ig      = (const float*)d_in[11];
    const float* W_fg      = (const float*)d_in[12];
    const float* b_fg      = (const float*)d_in[13];
    const float* mhln_w    = (const float*)d_in[14];
    const float* skip      = (const float*)d_in[15];
    const float* W_down    = (const float*)d_in[16];
    const float* ln_post_w = (const float*)d_in[17];
    float* out = (float*)d_out;

    void *pxp, *ph, *pup, *pq, *pk, *pvT, *pC, *phh, *phs, *py;
    void *pxr, *pWi, *pWu, *pWd, *pe, *ppm, *pn;
    cudaGetSymbolAddress(&pxp, g_xp);
    cudaGetSymbolAddress(&ph,  g_h);
    cudaGetSymbolAddress(&pup, g_up);
    cudaGetSymbolAddress(&pq,  g_q);
    cudaGetSymbolAddress(&pk,  g_k);
    cudaGetSymbolAddress(&pvT, g_vT);
    cudaGetSymbolAddress(&pC,  g_C);
    cudaGetSymbolAddress(&phh, g_hh);
    cudaGetSymbolAddress(&phs, g_hs);
    cudaGetSymbolAddress(&py,  g_y);
    cudaGetSymbolAddress(&pxr, g_xr);
    cudaGetSymbolAddress(&pWi, g_Wi);
    cudaGetSymbolAddress(&pWu, g_Wu);
    cudaGetSymbolAddress(&pWd, g_Wd);
    cudaGetSymbolAddress(&pe,  g_e);
    cudaGetSymbolAddress(&ppm, g_pm);
    cudaGetSymbolAddress(&pn,  g_n);

    cudaFuncSetAttribute(mma_gemm<0>, cudaFuncAttributeMaxDynamicSharedMemorySize, GSMEM);
    cudaFuncSetAttribute(mma_gemm<2>, cudaFuncAttributeMaxDynamicSharedMemorySize, GSMEM);
    cudaFuncSetAttribute(qk_fused,    cudaFuncAttributeMaxDynamicSharedMemorySize, QKSMEM);

    // 0. prep: fp16 operands, zero g_n
    {
        int total = ROWS * FIN / 4 + Ee * FIN / 4 + 2 * INNER * Ee / 4
                  + Ee * INNER / 4 + BNH * Ss / 4;
        prep_all<<<(total + 255) / 256, 256>>>(x, W_in, W_up, W_down);
    }

    // 1. xp = x @ W_in^T + b_in
    mma_gemm<0><<<dim3(Ee / 128, ROWS / 128, 1), NTHR, GSMEM>>>(
        (const __half*)pxr, (const __half*)pWi, (float*)pxp, b_in,
        FIN, FIN, FIN, Ee, 0, 0, 0, 0, 0, 0);

    // 2. h = LN(xp) -> fp16
    ln_rows_h<<<ROWS, 256>>>((const float*)pxp, ln1_w, (__half*)ph, Ee);

    // 3. up = h @ W_up^T
    mma_gemm<0><<<dim3(2 * INNER / 128, ROWS / 128, 1), NTHR, GSMEM>>>(
        (const __half*)ph, (const __half*)pWu, (float*)pup, nullptr,
        Ee, Ee, Ee, 2 * INNER, 0, 0, 0, 0, 0, 0);

    // 4. fused conv+SiLU+headwise
    conv_head<<<ROWS, 256>>>(conv_w, conv_b, Wq, Wk, Wv);

    // 5. gates
    gates<<<ROWS, 256>>>(W_ig, b_ig, W_fg, b_fg);

    // 6. parallel gate scan
    gate_scan_par<<<BNH, 1024>>>();

    // 7. fused QK^T * decay + rowsum; dead causal blocks transpose v -> vT
    qk_fused<<<dim3(Ss / 128, Ss / 128, BNH), NTHR, QKSMEM>>>(
        (const __half*)pq, (const __half*)pk, (__half*)pC,
        (const float*)pe, (const float*)ppm, (float*)pn);

    // 8. hh = C @ vT^T per head (K limited to causal extent)
    mma_gemm<2><<<dim3(DHd / 128, Ss / 128, BNH), NTHR, GSMEM>>>(
        (const __half*)pC, (const __half*)pvT, (float*)phh, nullptr,
        Ss, Ss, Ss, DHd,
        4L * Ss * Ss, (long)Ss * Ss,
        4L * DHd * Ss, (long)DHd * Ss,
        4L * Ss * DHd, (long)Ss * DHd);

    // 9. per-head LN + 1/n + combine
    mhln_combine<<<dim3(Ss, BNH), 256>>>(mhln_w, skip);

    // 10. y = h_state @ W_down^T
    mma_gemm<0><<<dim3(Ee / 128, ROWS / 128, 1), NTHR, GSMEM>>>(
        (const __half*)phs, (const __half*)pWd, (float*)py, nullptr,
        INNER, INNER, INNER, Ee, 0, 0, 0, 0, 0, 0);

    // 11. out = LN(res + y)
    add_ln_out<<<ROWS, 256>>>(ln_post_w, out);
}